// round 3
// baseline (speedup 1.0000x reference)
#include <cuda_runtime.h>
#include <cstdint>

// ---------------------------------------------------------------------------
// MultiScaleDETR deformable attention, fp32 reference-exact pipeline.
// B=4, Q=8400, D=256, nH=8, hd=32, L=3 (80x80, 40x40, 20x20), P=4.
// ---------------------------------------------------------------------------

#define B_    4
#define Q_    8400
#define D_    256
#define NH_   8
#define HD_   32
#define NL_   3
#define NP_   4
#define S_    8400           // 6400 + 1600 + 400
#define MQ_   (B_ * Q_)      // 33600

// Scratch (device globals: allowed; no runtime allocation).
__device__ float g_V  [B_ * S_ * D_];   // value projection, [b][s][d], d = h*32+c
__device__ float g_OFF[MQ_ * 192];      // raw offset logits  [bq][(h*L+l)*P+p, 2]
__device__ float g_ATT[MQ_ * 96];       // raw attn logits    [bq][h*12 + l*4+p]
__device__ float g_MID[MQ_ * D_];       // attention output pre-W_out

// ---------------------------------------------------------------------------
// Tiled SGEMM: 64x64x16 tile, 256 threads, 4x4 micro-tile per thread.
// ---------------------------------------------------------------------------
#define BM 64
#define BN 64
#define BK 16

// C[m,n] = sum_k A[m*K+k] * Bm[k*N+n] + bias[n]   (A row-major MxK)
__global__ void gemm_nn(const float* __restrict__ A, const float* __restrict__ Bm,
                        const float* __restrict__ bias, float* __restrict__ C,
                        int M, int N, int K) {
    __shared__ __align__(16) float As[BK][BM + 4];
    __shared__ __align__(16) float Bs[BK][BN];
    const int tid = threadIdx.x;
    const int tx = tid & 15, ty = tid >> 4;
    const int m0 = blockIdx.x * BM;
    const int n0 = blockIdx.y * BN;

    const int arow = tid >> 2;          // 0..63
    const int acol = (tid & 3) * 4;     // 0,4,8,12
    const int brow = tid >> 4;          // 0..15
    const int bcol = (tid & 15) * 4;    // 0..60

    float acc[4][4] = {};

    for (int k0 = 0; k0 < K; k0 += BK) {
        float4 a4 = make_float4(0.f, 0.f, 0.f, 0.f);
        int gm = m0 + arow;
        if (gm < M)
            a4 = *reinterpret_cast<const float4*>(A + (size_t)gm * K + k0 + acol);
        As[acol + 0][arow] = a4.x;
        As[acol + 1][arow] = a4.y;
        As[acol + 2][arow] = a4.z;
        As[acol + 3][arow] = a4.w;

        float4 b4 = make_float4(0.f, 0.f, 0.f, 0.f);
        int gn = n0 + bcol;
        if (gn < N)   // N is a multiple of 4, gn is a multiple of 4 -> full float4 safe
            b4 = *reinterpret_cast<const float4*>(Bm + (size_t)(k0 + brow) * N + gn);
        *reinterpret_cast<float4*>(&Bs[brow][bcol]) = b4;

        __syncthreads();
#pragma unroll
        for (int k = 0; k < BK; ++k) {
            float4 av = *reinterpret_cast<const float4*>(&As[k][ty * 4]);
            float4 bv = *reinterpret_cast<const float4*>(&Bs[k][tx * 4]);
            float a[4] = {av.x, av.y, av.z, av.w};
            float bb[4] = {bv.x, bv.y, bv.z, bv.w};
#pragma unroll
            for (int i = 0; i < 4; ++i)
#pragma unroll
                for (int j = 0; j < 4; ++j)
                    acc[i][j] = fmaf(a[i], bb[j], acc[i][j]);
        }
        __syncthreads();
    }

#pragma unroll
    for (int i = 0; i < 4; ++i) {
        int gm = m0 + ty * 4 + i;
        if (gm >= M) continue;
#pragma unroll
        for (int j = 0; j < 4; ++j) {
            int gn = n0 + tx * 4 + j;
            if (gn < N) C[(size_t)gm * N + gn] = acc[i][j] + bias[gn];
        }
    }
}

// Value projection: C[(b*S + sbase + m)*256 + n] = sum_k feat[b][k][m] * W[k*N+n] + bias[n]
// feat per batch: [K=256][M=HW], m contiguous. blockIdx.z = batch.
__global__ void gemm_tn_val(const float* __restrict__ feat, const float* __restrict__ W,
                            const float* __restrict__ bias, int M /*HW*/, int sbase) {
    __shared__ __align__(16) float As[BK][BM + 4];
    __shared__ __align__(16) float Bs[BK][BN];
    const int tid = threadIdx.x;
    const int tx = tid & 15, ty = tid >> 4;
    const int m0 = blockIdx.x * BM;
    const int n0 = blockIdx.y * BN;
    const int b  = blockIdx.z;
    const int K = D_, N = D_;

    const float* A = feat + (size_t)b * K * M;   // A[k][m], lda = M

    const int lrow = tid >> 4;          // 0..15  (k within tile)
    const int lcol = (tid & 15) * 4;    // 0..60  (m within tile)

    float acc[4][4] = {};

    for (int k0 = 0; k0 < K; k0 += BK) {
        float4 a4 = make_float4(0.f, 0.f, 0.f, 0.f);
        int gm = m0 + lcol;
        if (gm < M)  // M multiple of 4, gm multiple of 4 -> full float4 safe
            a4 = *reinterpret_cast<const float4*>(A + (size_t)(k0 + lrow) * M + gm);
        *reinterpret_cast<float4*>(&As[lrow][lcol]) = a4;

        float4 b4 = *reinterpret_cast<const float4*>(W + (size_t)(k0 + lrow) * N + n0 + lcol);
        *reinterpret_cast<float4*>(&Bs[lrow][lcol]) = b4;

        __syncthreads();
#pragma unroll
        for (int k = 0; k < BK; ++k) {
            float4 av = *reinterpret_cast<const float4*>(&As[k][ty * 4]);
            float4 bv = *reinterpret_cast<const float4*>(&Bs[k][tx * 4]);
            float a[4] = {av.x, av.y, av.z, av.w};
            float bb[4] = {bv.x, bv.y, bv.z, bv.w};
#pragma unroll
            for (int i = 0; i < 4; ++i)
#pragma unroll
                for (int j = 0; j < 4; ++j)
                    acc[i][j] = fmaf(a[i], bb[j], acc[i][j]);
        }
        __syncthreads();
    }

#pragma unroll
    for (int i = 0; i < 4; ++i) {
        int gm = m0 + ty * 4 + i;
        if (gm >= M) continue;
        size_t crow = ((size_t)b * S_ + sbase + gm) * D_;
#pragma unroll
        for (int j = 0; j < 4; ++j) {
            int gn = n0 + tx * 4 + j;
            g_V[crow + gn] = acc[i][j] + bias[gn];
        }
    }
}

// ---------------------------------------------------------------------------
// Sampling: one warp per (b, q, h). lane = channel within head (hd=32).
// ---------------------------------------------------------------------------
__global__ void sample_kernel(const float* __restrict__ ref) {
    const int warp = (blockIdx.x * blockDim.x + threadIdx.x) >> 5;
    const int lane = threadIdx.x & 31;
    if (warp >= MQ_ * NH_) return;

    const int h  = warp & 7;
    const int bq = warp >> 3;
    const int b  = bq / Q_;

    const float rx = ref[(size_t)bq * 2 + 0];
    const float ry = ref[(size_t)bq * 2 + 1];

    const float* offp = g_OFF + (size_t)bq * 192 + h * 24;   // (l*4+p)*2 + xy
    const float* attp = g_ATT + (size_t)bq * 96 + h * 12;    // l*4+p

    // softmax over the 12 (level, point) logits (redundant per lane; broadcast loads)
    float araw[12];
    float amax = -1e30f;
#pragma unroll
    for (int i = 0; i < 12; ++i) { araw[i] = attp[i]; amax = fmaxf(amax, araw[i]); }
    float asum = 0.f;
#pragma unroll
    for (int i = 0; i < 12; ++i) { araw[i] = __expf(araw[i] - amax); asum += araw[i]; }
    const float ainv = 1.f / asum;

    const int   Hls[3] = {80, 40, 20};
    const int   Wls[3] = {80, 40, 20};
    const int   bas[3] = {0, 6400, 8000};

    const float* Vb = g_V + (size_t)b * S_ * D_ + h * HD_ + lane;

    float acc = 0.f;
#pragma unroll
    for (int l = 0; l < NL_; ++l) {
        const int Hl = Hls[l], Wl = Wls[l], base = bas[l];
#pragma unroll
        for (int p = 0; p < NP_; ++p) {
            const float ox = tanhf(offp[(l * 4 + p) * 2 + 0]) * 0.5f;
            const float oy = tanhf(offp[(l * 4 + p) * 2 + 1]) * 0.5f;
            const float ix = (rx + ox) * (float)Wl - 0.5f;
            const float iy = (ry + oy) * (float)Hl - 0.5f;
            const float x0f = floorf(ix), y0f = floorf(iy);
            const int x0 = (int)x0f, y0 = (int)y0f;
            const float fx = ix - x0f, fy = iy - y0f;
            const float w = araw[l * 4 + p] * ainv;
            const float w00 = w * (1.f - fx) * (1.f - fy);
            const float w01 = w * fx * (1.f - fy);
            const float w10 = w * (1.f - fx) * fy;
            const float w11 = w * fx * fy;

            const bool xin0 = (x0 >= 0) && (x0 < Wl);
            const bool xin1 = (x0 + 1 >= 0) && (x0 + 1 < Wl);
            const bool yin0 = (y0 >= 0) && (y0 < Hl);
            const bool yin1 = (y0 + 1 >= 0) && (y0 + 1 < Hl);

            if (xin0 && yin0) acc = fmaf(w00, Vb[(size_t)(base + y0 * Wl + x0) * D_], acc);
            if (xin1 && yin0) acc = fmaf(w01, Vb[(size_t)(base + y0 * Wl + x0 + 1) * D_], acc);
            if (xin0 && yin1) acc = fmaf(w10, Vb[(size_t)(base + (y0 + 1) * Wl + x0) * D_], acc);
            if (xin1 && yin1) acc = fmaf(w11, Vb[(size_t)(base + (y0 + 1) * Wl + x0 + 1) * D_], acc);
        }
    }

    g_MID[(size_t)bq * D_ + h * HD_ + lane] = acc;
}

// ---------------------------------------------------------------------------
// Launch
// ---------------------------------------------------------------------------
extern "C" void kernel_launch(void* const* d_in, const int* in_sizes, int n_in,
                              void* d_out, int out_size) {
    const float* query = (const float*)d_in[0];
    const float* feat0 = (const float*)d_in[1];
    const float* feat1 = (const float*)d_in[2];
    const float* feat2 = (const float*)d_in[3];
    const float* refp  = (const float*)d_in[4];
    const float* W_off = (const float*)d_in[5];
    const float* b_off = (const float*)d_in[6];
    const float* W_att = (const float*)d_in[7];
    const float* b_att = (const float*)d_in[8];
    const float* W_val = (const float*)d_in[9];
    const float* b_val = (const float*)d_in[10];
    const float* W_out = (const float*)d_in[11];
    const float* b_out = (const float*)d_in[12];
    float* out = (float*)d_out;

    float* pV;   cudaGetSymbolAddress((void**)&pV,   g_V);
    float* pOFF; cudaGetSymbolAddress((void**)&pOFF, g_OFF);
    float* pATT; cudaGetSymbolAddress((void**)&pATT, g_ATT);
    float* pMID; cudaGetSymbolAddress((void**)&pMID, g_MID);

    // 1) value projection per level  (feat^T @ W_val + b_val)
    {
        dim3 blk(256);
        dim3 g0((6400 + BM - 1) / BM, D_ / BN, B_);
        gemm_tn_val<<<g0, blk>>>(feat0, W_val, b_val, 6400, 0);
        dim3 g1((1600 + BM - 1) / BM, D_ / BN, B_);
        gemm_tn_val<<<g1, blk>>>(feat1, W_val, b_val, 1600, 6400);
        dim3 g2((400 + BM - 1) / BM, D_ / BN, B_);
        gemm_tn_val<<<g2, blk>>>(feat2, W_val, b_val, 400, 8000);
    }

    // 2) offset & attention logits
    {
        dim3 blk(256);
        dim3 go(MQ_ / BM, (192 + BN - 1) / BN);
        gemm_nn<<<go, blk>>>(query, W_off, b_off, pOFF, MQ_, 192, D_);
        dim3 ga(MQ_ / BM, (96 + BN - 1) / BN);
        gemm_nn<<<ga, blk>>>(query, W_att, b_att, pATT, MQ_, 96, D_);
    }

    // 3) bilinear sampling + softmax weighting -> MID
    {
        int nwarps = MQ_ * NH_;                 // 268800
        int threads = 256;                      // 8 warps / block
        int blocks = (nwarps * 32 + threads - 1) / threads;
        sample_kernel<<<blocks, threads>>>(refp);
    }

    // 4) output projection
    {
        dim3 blk(256);
        dim3 g(MQ_ / BM, D_ / BN);
        gemm_nn<<<g, blk>>>(pMID, W_out, b_out, out, MQ_, D_, D_);
    }
}

// round 4
// speedup vs baseline: 1.5668x; 1.5668x over previous
#include <cuda_runtime.h>
#include <cstdint>

// ---------------------------------------------------------------------------
// MultiScaleDETR deformable attention.
// B=4, Q=8400, D=256, nH=8, hd=32, L=3 (80x80,40x40,20x20), P=4.
// tf32 tensor-core GEMMs for value/attn/output; fp32 FFMA for offsets
// (sampling amplifies offset errors ~100x, so offsets stay fp32).
// ---------------------------------------------------------------------------

#define B_    4
#define Q_    8400
#define D_    256
#define NH_   8
#define HD_   32
#define NL_   3
#define NP_   4
#define S_    8400
#define MQ_   (B_ * Q_)      // 33600

__device__ float g_V  [B_ * S_ * D_];   // value projection [b][s][d]
__device__ float g_OFF[MQ_ * 192];      // tanh(offset_logit)*0.5
__device__ float g_ATT[MQ_ * 96];       // attn logits -> softmax'ed in place
__device__ float g_MID[MQ_ * D_];       // attention output pre-W_out

// ---------------------------------------------------------------------------
// tf32 helpers
// ---------------------------------------------------------------------------
__device__ __forceinline__ uint32_t f2tf32(float f) {
    uint32_t u;
    asm("cvt.rna.tf32.f32 %0, %1;" : "=r"(u) : "f"(f));
    return u;
}

__device__ __forceinline__ void mma_tf32(float* d, const uint32_t* a, const uint32_t* b) {
    asm volatile(
        "mma.sync.aligned.m16n8k8.row.col.f32.tf32.tf32.f32 "
        "{%0,%1,%2,%3}, {%4,%5,%6,%7}, {%8,%9}, {%0,%1,%2,%3};\n"
        : "+f"(d[0]), "+f"(d[1]), "+f"(d[2]), "+f"(d[3])
        : "r"(a[0]), "r"(a[1]), "r"(a[2]), "r"(a[3]), "r"(b[0]), "r"(b[1]));
}

// ---------------------------------------------------------------------------
// tf32 GEMM (NN): C[M,N] = A[M,K](row) @ B[K,N](row) + bias
// 128x64x16 tile, 256 threads = 8 warps (4m x 2n), warp tile 32x32,
// mma m16n8k8: 2 m-frags x 4 n-frags x 2 k-steps.
// ---------------------------------------------------------------------------
__global__ void gemm_nn_tf32(const float* __restrict__ A, const float* __restrict__ Bm,
                             const float* __restrict__ bias, float* __restrict__ C,
                             int M, int N, int K) {
    __shared__ __align__(16) uint32_t As[128][20];  // [m][k], pitch 20 -> conflict-free frags
    __shared__ __align__(16) uint32_t Bs[16][72];   // [k][n], pitch 72 -> conflict-free frags
    const int tid  = threadIdx.x;
    const int lane = tid & 31;
    const int warp = tid >> 5;
    const int g  = lane >> 2, t4 = lane & 3;
    const int wm = warp >> 1, wn = warp & 1;
    const int m0 = blockIdx.x * 128, n0 = blockIdx.y * 64;

    float acc[2][4][4] = {};

    for (int k0 = 0; k0 < K; k0 += 16) {
        // stage A: 128x16, two passes of 64 rows, float4 along k
#pragma unroll
        for (int p = 0; p < 2; ++p) {
            int m  = p * 64 + (tid >> 2);
            int kk = (tid & 3) * 4;
            float4 a4 = make_float4(0.f, 0.f, 0.f, 0.f);
            int gm = m0 + m;
            if (gm < M) a4 = *reinterpret_cast<const float4*>(A + (size_t)gm * K + k0 + kk);
            uint4 u;
            u.x = f2tf32(a4.x); u.y = f2tf32(a4.y); u.z = f2tf32(a4.z); u.w = f2tf32(a4.w);
            *reinterpret_cast<uint4*>(&As[m][kk]) = u;
        }
        // stage B: 16x64, float4 along n
        {
            int kr = tid >> 4, nn = (tid & 15) * 4;
            float4 b4 = make_float4(0.f, 0.f, 0.f, 0.f);
            if (n0 + nn < N)
                b4 = *reinterpret_cast<const float4*>(Bm + (size_t)(k0 + kr) * N + n0 + nn);
            uint4 u;
            u.x = f2tf32(b4.x); u.y = f2tf32(b4.y); u.z = f2tf32(b4.z); u.w = f2tf32(b4.w);
            *reinterpret_cast<uint4*>(&Bs[kr][nn]) = u;
        }
        __syncthreads();
#pragma unroll
        for (int ks = 0; ks < 2; ++ks) {
            const int kb = ks * 8;
            uint32_t af[2][4], bf[4][2];
#pragma unroll
            for (int mt = 0; mt < 2; ++mt) {
                int rb = wm * 32 + mt * 16;
                af[mt][0] = As[rb + g    ][kb + t4    ];
                af[mt][1] = As[rb + g + 8][kb + t4    ];
                af[mt][2] = As[rb + g    ][kb + t4 + 4];
                af[mt][3] = As[rb + g + 8][kb + t4 + 4];
            }
#pragma unroll
            for (int nt = 0; nt < 4; ++nt) {
                int cb = wn * 32 + nt * 8;
                bf[nt][0] = Bs[kb + t4    ][cb + g];
                bf[nt][1] = Bs[kb + t4 + 4][cb + g];
            }
#pragma unroll
            for (int mt = 0; mt < 2; ++mt)
#pragma unroll
                for (int nt = 0; nt < 4; ++nt)
                    mma_tf32(acc[mt][nt], af[mt], bf[nt]);
        }
        __syncthreads();
    }

#pragma unroll
    for (int mt = 0; mt < 2; ++mt)
#pragma unroll
        for (int nt = 0; nt < 4; ++nt) {
            int r = m0 + wm * 32 + mt * 16 + g;
            int c = n0 + wn * 32 + nt * 8 + t4 * 2;
            if (c < N) {
                float b0 = bias[c], b1 = bias[c + 1];
                if (r < M) {
                    C[(size_t)r * N + c]     = acc[mt][nt][0] + b0;
                    C[(size_t)r * N + c + 1] = acc[mt][nt][1] + b1;
                }
                if (r + 8 < M) {
                    C[(size_t)(r + 8) * N + c]     = acc[mt][nt][2] + b0;
                    C[(size_t)(r + 8) * N + c + 1] = acc[mt][nt][3] + b1;
                }
            }
        }
}

// ---------------------------------------------------------------------------
// tf32 GEMM (TN) for value projection:
// g_V[(b*S + sbase + m)*256 + n] = sum_k feat[b][k][m] * W[k][n] + bias[n]
// A stored [k][m] in gmem (m contiguous) -> As kept [k][m].
// ---------------------------------------------------------------------------
__global__ void gemm_tn_tf32(const float* __restrict__ feat, const float* __restrict__ W,
                             const float* __restrict__ bias, int M /*HW*/, int sbase) {
    __shared__ __align__(16) uint32_t As[16][136];  // [k][m], pitch 136 -> conflict-free
    __shared__ __align__(16) uint32_t Bs[16][72];   // [k][n]
    const int tid  = threadIdx.x;
    const int lane = tid & 31;
    const int warp = tid >> 5;
    const int g  = lane >> 2, t4 = lane & 3;
    const int wm = warp >> 1, wn = warp & 1;
    const int m0 = blockIdx.x * 128, n0 = blockIdx.y * 64;
    const int b  = blockIdx.z;
    const int K = D_, N = D_;

    const float* A = feat + (size_t)b * K * M;   // A[k][m], lda = M

    float acc[2][4][4] = {};

    for (int k0 = 0; k0 < K; k0 += 16) {
        // stage A: 16(k) x 128(m); two passes of 64 m-cols, float4 along m
#pragma unroll
        for (int p = 0; p < 2; ++p) {
            int m = p * 64 + (tid & 15) * 4;
            int k = tid >> 4;
            float4 a4 = make_float4(0.f, 0.f, 0.f, 0.f);
            if (m0 + m < M)
                a4 = *reinterpret_cast<const float4*>(A + (size_t)(k0 + k) * M + m0 + m);
            uint4 u;
            u.x = f2tf32(a4.x); u.y = f2tf32(a4.y); u.z = f2tf32(a4.z); u.w = f2tf32(a4.w);
            *reinterpret_cast<uint4*>(&As[k][m]) = u;
        }
        // stage B (W_val row-major 256x256)
        {
            int kr = tid >> 4, nn = (tid & 15) * 4;
            float4 b4 = *reinterpret_cast<const float4*>(W + (size_t)(k0 + kr) * N + n0 + nn);
            uint4 u;
            u.x = f2tf32(b4.x); u.y = f2tf32(b4.y); u.z = f2tf32(b4.z); u.w = f2tf32(b4.w);
            *reinterpret_cast<uint4*>(&Bs[kr][nn]) = u;
        }
        __syncthreads();
#pragma unroll
        for (int ks = 0; ks < 2; ++ks) {
            const int kb = ks * 8;
            uint32_t af[2][4], bf[4][2];
#pragma unroll
            for (int mt = 0; mt < 2; ++mt) {
                int rb = wm * 32 + mt * 16;
                af[mt][0] = As[kb + t4    ][rb + g    ];
                af[mt][1] = As[kb + t4    ][rb + g + 8];
                af[mt][2] = As[kb + t4 + 4][rb + g    ];
                af[mt][3] = As[kb + t4 + 4][rb + g + 8];
            }
#pragma unroll
            for (int nt = 0; nt < 4; ++nt) {
                int cb = wn * 32 + nt * 8;
                bf[nt][0] = Bs[kb + t4    ][cb + g];
                bf[nt][1] = Bs[kb + t4 + 4][cb + g];
            }
#pragma unroll
            for (int mt = 0; mt < 2; ++mt)
#pragma unroll
                for (int nt = 0; nt < 4; ++nt)
                    mma_tf32(acc[mt][nt], af[mt], bf[nt]);
        }
        __syncthreads();
    }

#pragma unroll
    for (int mt = 0; mt < 2; ++mt)
#pragma unroll
        for (int nt = 0; nt < 4; ++nt) {
            int r = m0 + wm * 32 + mt * 16 + g;
            int c = n0 + wn * 32 + nt * 8 + t4 * 2;
            float b0 = bias[c], b1 = bias[c + 1];
            if (r < M) {
                size_t row = ((size_t)b * S_ + sbase + r) * D_;
                g_V[row + c]     = acc[mt][nt][0] + b0;
                g_V[row + c + 1] = acc[mt][nt][1] + b1;
            }
            if (r + 8 < M) {
                size_t row = ((size_t)b * S_ + sbase + r + 8) * D_;
                g_V[row + c]     = acc[mt][nt][2] + b0;
                g_V[row + c + 1] = acc[mt][nt][3] + b1;
            }
        }
}

// ---------------------------------------------------------------------------
// fp32 FFMA GEMM (precision-critical offset logits), fused tanh(x)*0.5 epilogue
// 64x64x16 tile, 256 threads, 4x4 micro-tile.
// ---------------------------------------------------------------------------
#define BM 64
#define BN 64
#define BK 16

__global__ void gemm_nn_tanh(const float* __restrict__ A, const float* __restrict__ Bm,
                             const float* __restrict__ bias, float* __restrict__ C,
                             int M, int N, int K) {
    __shared__ __align__(16) float As[BK][BM + 4];
    __shared__ __align__(16) float Bs[BK][BN];
    const int tid = threadIdx.x;
    const int tx = tid & 15, ty = tid >> 4;
    const int m0 = blockIdx.x * BM;
    const int n0 = blockIdx.y * BN;

    const int arow = tid >> 2;
    const int acol = (tid & 3) * 4;
    const int brow = tid >> 4;
    const int bcol = (tid & 15) * 4;

    float acc[4][4] = {};

    for (int k0 = 0; k0 < K; k0 += BK) {
        float4 a4 = make_float4(0.f, 0.f, 0.f, 0.f);
        int gm = m0 + arow;
        if (gm < M)
            a4 = *reinterpret_cast<const float4*>(A + (size_t)gm * K + k0 + acol);
        As[acol + 0][arow] = a4.x;
        As[acol + 1][arow] = a4.y;
        As[acol + 2][arow] = a4.z;
        As[acol + 3][arow] = a4.w;

        float4 b4 = make_float4(0.f, 0.f, 0.f, 0.f);
        int gn = n0 + bcol;
        if (gn < N)
            b4 = *reinterpret_cast<const float4*>(Bm + (size_t)(k0 + brow) * N + gn);
        *reinterpret_cast<float4*>(&Bs[brow][bcol]) = b4;

        __syncthreads();
#pragma unroll
        for (int k = 0; k < BK; ++k) {
            float4 av = *reinterpret_cast<const float4*>(&As[k][ty * 4]);
            float4 bv = *reinterpret_cast<const float4*>(&Bs[k][tx * 4]);
            float a[4] = {av.x, av.y, av.z, av.w};
            float bb[4] = {bv.x, bv.y, bv.z, bv.w};
#pragma unroll
            for (int i = 0; i < 4; ++i)
#pragma unroll
                for (int j = 0; j < 4; ++j)
                    acc[i][j] = fmaf(a[i], bb[j], acc[i][j]);
        }
        __syncthreads();
    }

#pragma unroll
    for (int i = 0; i < 4; ++i) {
        int gm = m0 + ty * 4 + i;
        if (gm >= M) continue;
#pragma unroll
        for (int j = 0; j < 4; ++j) {
            int gn = n0 + tx * 4 + j;
            if (gn < N)
                C[(size_t)gm * N + gn] = tanhf(acc[i][j] + bias[gn]) * 0.5f;
        }
    }
}

// ---------------------------------------------------------------------------
// Softmax over 12 (level,point) logits: one thread per (bq, h); in place.
// ---------------------------------------------------------------------------
__global__ void softmax12(float* __restrict__ att) {
    int i = blockIdx.x * blockDim.x + threadIdx.x;
    if (i >= MQ_ * NH_) return;
    float* p = att + (size_t)(i >> 3) * 96 + (i & 7) * 12;
    float v[12], mx = -1e30f;
#pragma unroll
    for (int j = 0; j < 12; ++j) { v[j] = p[j]; mx = fmaxf(mx, v[j]); }
    float s = 0.f;
#pragma unroll
    for (int j = 0; j < 12; ++j) { v[j] = __expf(v[j] - mx); s += v[j]; }
    float inv = 1.f / s;
#pragma unroll
    for (int j = 0; j < 12; ++j) p[j] = v[j] * inv;
}

// ---------------------------------------------------------------------------
// Sampling: one warp per (b, q, h), lane = channel. Offsets pre-tanh'ed,
// weights pre-softmax'ed -> pure gather-accumulate.
// ---------------------------------------------------------------------------
__global__ void sample_kernel(const float* __restrict__ ref) {
    const int warp = (blockIdx.x * blockDim.x + threadIdx.x) >> 5;
    const int lane = threadIdx.x & 31;
    if (warp >= MQ_ * NH_) return;

    const int h  = warp & 7;
    const int bq = warp >> 3;
    const int b  = bq / Q_;

    const float rx = __ldg(ref + (size_t)bq * 2 + 0);
    const float ry = __ldg(ref + (size_t)bq * 2 + 1);

    const float* offp = g_OFF + (size_t)bq * 192 + h * 24;
    const float* attp = g_ATT + (size_t)bq * 96 + h * 12;

    const int Wls[3] = {80, 40, 20};
    const int bas[3] = {0, 6400, 8000};

    const float* Vb = g_V + (size_t)b * S_ * D_ + h * HD_ + lane;

    float acc = 0.f;
#pragma unroll
    for (int l = 0; l < NL_; ++l) {
        const int Wl = Wls[l], base = bas[l];
        const float Wlf = (float)Wl;
#pragma unroll
        for (int p = 0; p < NP_; ++p) {
            const float ox = __ldg(offp + (l * 4 + p) * 2 + 0);
            const float oy = __ldg(offp + (l * 4 + p) * 2 + 1);
            const float w  = __ldg(attp + l * 4 + p);
            const float ix = (rx + ox) * Wlf - 0.5f;
            const float iy = (ry + oy) * Wlf - 0.5f;
            const float x0f = floorf(ix), y0f = floorf(iy);
            const int x0 = (int)x0f, y0 = (int)y0f;
            const float fx = ix - x0f, fy = iy - y0f;
            const float w00 = w * (1.f - fx) * (1.f - fy);
            const float w01 = w * fx * (1.f - fy);
            const float w10 = w * (1.f - fx) * fy;
            const float w11 = w * fx * fy;

            const bool xin0 = (x0 >= 0) && (x0 < Wl);
            const bool xin1 = (x0 + 1 >= 0) && (x0 + 1 < Wl);
            const bool yin0 = (y0 >= 0) && (y0 < Wl);
            const bool yin1 = (y0 + 1 >= 0) && (y0 + 1 < Wl);

            if (xin0 && yin0) acc = fmaf(w00, Vb[(size_t)(base + y0 * Wl + x0) * D_], acc);
            if (xin1 && yin0) acc = fmaf(w01, Vb[(size_t)(base + y0 * Wl + x0 + 1) * D_], acc);
            if (xin0 && yin1) acc = fmaf(w10, Vb[(size_t)(base + (y0 + 1) * Wl + x0) * D_], acc);
            if (xin1 && yin1) acc = fmaf(w11, Vb[(size_t)(base + (y0 + 1) * Wl + x0 + 1) * D_], acc);
        }
    }

    g_MID[(size_t)bq * D_ + h * HD_ + lane] = acc;
}

// ---------------------------------------------------------------------------
// Launch
// ---------------------------------------------------------------------------
extern "C" void kernel_launch(void* const* d_in, const int* in_sizes, int n_in,
                              void* d_out, int out_size) {
    const float* query = (const float*)d_in[0];
    const float* feat0 = (const float*)d_in[1];
    const float* feat1 = (const float*)d_in[2];
    const float* feat2 = (const float*)d_in[3];
    const float* refp  = (const float*)d_in[4];
    const float* W_off = (const float*)d_in[5];
    const float* b_off = (const float*)d_in[6];
    const float* W_att = (const float*)d_in[7];
    const float* b_att = (const float*)d_in[8];
    const float* W_val = (const float*)d_in[9];
    const float* b_val = (const float*)d_in[10];
    const float* W_out = (const float*)d_in[11];
    const float* b_out = (const float*)d_in[12];
    float* out = (float*)d_out;

    float* pOFF; cudaGetSymbolAddress((void**)&pOFF, g_OFF);
    float* pATT; cudaGetSymbolAddress((void**)&pATT, g_ATT);
    float* pMID; cudaGetSymbolAddress((void**)&pMID, g_MID);

    dim3 blk(256);

    // 1) value projection per level (tf32 tensor cores)
    gemm_tn_tf32<<<dim3(50, 4, B_), blk>>>(feat0, W_val, b_val, 6400, 0);
    gemm_tn_tf32<<<dim3(13, 4, B_), blk>>>(feat1, W_val, b_val, 1600, 6400);
    gemm_tn_tf32<<<dim3( 4, 4, B_), blk>>>(feat2, W_val, b_val,  400, 8000);

    // 2) offset logits (fp32 FFMA, fused tanh*0.5)
    gemm_nn_tanh<<<dim3(MQ_ / BM, 3), blk>>>(query, W_off, b_off, pOFF, MQ_, 192, D_);

    // 3) attention logits (tf32) + softmax
    gemm_nn_tf32<<<dim3((MQ_ + 127) / 128, 2), blk>>>(query, W_att, b_att, pATT, MQ_, 96, D_);
    softmax12<<<(MQ_ * NH_ + 255) / 256, 256>>>(pATT);

    // 4) bilinear sampling -> MID
    {
        int nwarps = MQ_ * NH_;
        int blocks = (nwarps * 32 + 255) / 256;
        sample_kernel<<<blocks, 256>>>(refp);
    }

    // 5) output projection (tf32)
    gemm_nn_tf32<<<dim3((MQ_ + 127) / 128, 4), blk>>>(pMID, W_out, b_out, out, MQ_, D_, D_);
}

// round 5
// speedup vs baseline: 1.5733x; 1.0042x over previous
#include <cuda_runtime.h>
#include <cstdint>

// ---------------------------------------------------------------------------
// MultiScaleDETR deformable attention.
// B=4, Q=8400, D=256, nH=8, hd=32, L=3 (80x80,40x40,20x20), P=4.
// tf32 tensor-core GEMMs for value/attn/output; fp32 FFMA for offsets
// (sampling amplifies offset errors ~100x, so offsets stay fp32).
// ---------------------------------------------------------------------------

#define B_    4
#define Q_    8400
#define D_    256
#define NH_   8
#define HD_   32
#define NL_   3
#define NP_   4
#define S_    8400
#define MQ_   (B_ * Q_)      // 33600

__device__ float g_V  [B_ * S_ * D_];   // value projection [b][s][d]
__device__ float g_OFF[MQ_ * 192];      // tanh(offset_logit)*0.5
__device__ float g_ATT[MQ_ * 96];       // attn logits -> softmax'ed in place
__device__ float g_MID[MQ_ * D_];       // attention output pre-W_out

// ---------------------------------------------------------------------------
// tf32 helpers
// ---------------------------------------------------------------------------
__device__ __forceinline__ uint32_t f2tf32(float f) {
    uint32_t u;
    asm("cvt.rna.tf32.f32 %0, %1;" : "=r"(u) : "f"(f));
    return u;
}

__device__ __forceinline__ void mma_tf32(float* d, const uint32_t* a, const uint32_t* b) {
    asm volatile(
        "mma.sync.aligned.m16n8k8.row.col.f32.tf32.tf32.f32 "
        "{%0,%1,%2,%3}, {%4,%5,%6,%7}, {%8,%9}, {%0,%1,%2,%3};\n"
        : "+f"(d[0]), "+f"(d[1]), "+f"(d[2]), "+f"(d[3])
        : "r"(a[0]), "r"(a[1]), "r"(a[2]), "r"(a[3]), "r"(b[0]), "r"(b[1]));
}

// ---------------------------------------------------------------------------
// tf32 GEMM (NN): C[M,N] = A[M,K](row) @ B[K,N](row) + bias
// 128x64x16 tile, 256 threads = 8 warps (4m x 2n), warp tile 32x32,
// mma m16n8k8: 2 m-frags x 4 n-frags x 2 k-steps.
// ---------------------------------------------------------------------------
__global__ void gemm_nn_tf32(const float* __restrict__ A, const float* __restrict__ Bm,
                             const float* __restrict__ bias, float* __restrict__ C,
                             int M, int N, int K) {
    __shared__ __align__(16) uint32_t As[128][20];  // [m][k], pitch 20 -> conflict-free frags
    __shared__ __align__(16) uint32_t Bs[16][72];   // [k][n], pitch 72 -> conflict-free frags
    const int tid  = threadIdx.x;
    const int lane = tid & 31;
    const int warp = tid >> 5;
    const int g  = lane >> 2, t4 = lane & 3;
    const int wm = warp >> 1, wn = warp & 1;
    const int m0 = blockIdx.x * 128, n0 = blockIdx.y * 64;

    float acc[2][4][4] = {};

    for (int k0 = 0; k0 < K; k0 += 16) {
        // stage A: 128x16, two passes of 64 rows, float4 along k
#pragma unroll
        for (int p = 0; p < 2; ++p) {
            int m  = p * 64 + (tid >> 2);
            int kk = (tid & 3) * 4;
            float4 a4 = make_float4(0.f, 0.f, 0.f, 0.f);
            int gm = m0 + m;
            if (gm < M) a4 = *reinterpret_cast<const float4*>(A + (size_t)gm * K + k0 + kk);
            uint4 u;
            u.x = f2tf32(a4.x); u.y = f2tf32(a4.y); u.z = f2tf32(a4.z); u.w = f2tf32(a4.w);
            *reinterpret_cast<uint4*>(&As[m][kk]) = u;
        }
        // stage B: 16x64, float4 along n
        {
            int kr = tid >> 4, nn = (tid & 15) * 4;
            float4 b4 = make_float4(0.f, 0.f, 0.f, 0.f);
            if (n0 + nn < N)
                b4 = *reinterpret_cast<const float4*>(Bm + (size_t)(k0 + kr) * N + n0 + nn);
            uint4 u;
            u.x = f2tf32(b4.x); u.y = f2tf32(b4.y); u.z = f2tf32(b4.z); u.w = f2tf32(b4.w);
            *reinterpret_cast<uint4*>(&Bs[kr][nn]) = u;
        }
        __syncthreads();
#pragma unroll
        for (int ks = 0; ks < 2; ++ks) {
            const int kb = ks * 8;
            uint32_t af[2][4], bf[4][2];
#pragma unroll
            for (int mt = 0; mt < 2; ++mt) {
                int rb = wm * 32 + mt * 16;
                af[mt][0] = As[rb + g    ][kb + t4    ];
                af[mt][1] = As[rb + g + 8][kb + t4    ];
                af[mt][2] = As[rb + g    ][kb + t4 + 4];
                af[mt][3] = As[rb + g + 8][kb + t4 + 4];
            }
#pragma unroll
            for (int nt = 0; nt < 4; ++nt) {
                int cb = wn * 32 + nt * 8;
                bf[nt][0] = Bs[kb + t4    ][cb + g];
                bf[nt][1] = Bs[kb + t4 + 4][cb + g];
            }
#pragma unroll
            for (int mt = 0; mt < 2; ++mt)
#pragma unroll
                for (int nt = 0; nt < 4; ++nt)
                    mma_tf32(acc[mt][nt], af[mt], bf[nt]);
        }
        __syncthreads();
    }

#pragma unroll
    for (int mt = 0; mt < 2; ++mt)
#pragma unroll
        for (int nt = 0; nt < 4; ++nt) {
            int r = m0 + wm * 32 + mt * 16 + g;
            int c = n0 + wn * 32 + nt * 8 + t4 * 2;
            if (c < N) {
                float b0 = bias[c], b1 = bias[c + 1];
                if (r < M) {
                    C[(size_t)r * N + c]     = acc[mt][nt][0] + b0;
                    C[(size_t)r * N + c + 1] = acc[mt][nt][1] + b1;
                }
                if (r + 8 < M) {
                    C[(size_t)(r + 8) * N + c]     = acc[mt][nt][2] + b0;
                    C[(size_t)(r + 8) * N + c + 1] = acc[mt][nt][3] + b1;
                }
            }
        }
}

// ---------------------------------------------------------------------------
// tf32 GEMM (TN) for value projection:
// g_V[(b*S + sbase + m)*256 + n] = sum_k feat[b][k][m] * W[k][n] + bias[n]
// A stored [k][m] in gmem (m contiguous) -> As kept [k][m].
// ---------------------------------------------------------------------------
__global__ void gemm_tn_tf32(const float* __restrict__ feat, const float* __restrict__ W,
                             const float* __restrict__ bias, int M /*HW*/, int sbase) {
    __shared__ __align__(16) uint32_t As[16][136];  // [k][m], pitch 136 -> conflict-free
    __shared__ __align__(16) uint32_t Bs[16][72];   // [k][n]
    const int tid  = threadIdx.x;
    const int lane = tid & 31;
    const int warp = tid >> 5;
    const int g  = lane >> 2, t4 = lane & 3;
    const int wm = warp >> 1, wn = warp & 1;
    const int m0 = blockIdx.x * 128, n0 = blockIdx.y * 64;
    const int b  = blockIdx.z;
    const int K = D_, N = D_;

    const float* A = feat + (size_t)b * K * M;   // A[k][m], lda = M

    float acc[2][4][4] = {};

    for (int k0 = 0; k0 < K; k0 += 16) {
        // stage A: 16(k) x 128(m); two passes of 64 m-cols, float4 along m
#pragma unroll
        for (int p = 0; p < 2; ++p) {
            int m = p * 64 + (tid & 15) * 4;
            int k = tid >> 4;
            float4 a4 = make_float4(0.f, 0.f, 0.f, 0.f);
            if (m0 + m < M)
                a4 = *reinterpret_cast<const float4*>(A + (size_t)(k0 + k) * M + m0 + m);
            uint4 u;
            u.x = f2tf32(a4.x); u.y = f2tf32(a4.y); u.z = f2tf32(a4.z); u.w = f2tf32(a4.w);
            *reinterpret_cast<uint4*>(&As[k][m]) = u;
        }
        // stage B (W_val row-major 256x256)
        {
            int kr = tid >> 4, nn = (tid & 15) * 4;
            float4 b4 = *reinterpret_cast<const float4*>(W + (size_t)(k0 + kr) * N + n0 + nn);
            uint4 u;
            u.x = f2tf32(b4.x); u.y = f2tf32(b4.y); u.z = f2tf32(b4.z); u.w = f2tf32(b4.w);
            *reinterpret_cast<uint4*>(&Bs[kr][nn]) = u;
        }
        __syncthreads();
#pragma unroll
        for (int ks = 0; ks < 2; ++ks) {
            const int kb = ks * 8;
            uint32_t af[2][4], bf[4][2];
#pragma unroll
            for (int mt = 0; mt < 2; ++mt) {
                int rb = wm * 32 + mt * 16;
                af[mt][0] = As[kb + t4    ][rb + g    ];
                af[mt][1] = As[kb + t4    ][rb + g + 8];
                af[mt][2] = As[kb + t4 + 4][rb + g    ];
                af[mt][3] = As[kb + t4 + 4][rb + g + 8];
            }
#pragma unroll
            for (int nt = 0; nt < 4; ++nt) {
                int cb = wn * 32 + nt * 8;
                bf[nt][0] = Bs[kb + t4    ][cb + g];
                bf[nt][1] = Bs[kb + t4 + 4][cb + g];
            }
#pragma unroll
            for (int mt = 0; mt < 2; ++mt)
#pragma unroll
                for (int nt = 0; nt < 4; ++nt)
                    mma_tf32(acc[mt][nt], af[mt], bf[nt]);
        }
        __syncthreads();
    }

#pragma unroll
    for (int mt = 0; mt < 2; ++mt)
#pragma unroll
        for (int nt = 0; nt < 4; ++nt) {
            int r = m0 + wm * 32 + mt * 16 + g;
            int c = n0 + wn * 32 + nt * 8 + t4 * 2;
            float b0 = bias[c], b1 = bias[c + 1];
            if (r < M) {
                size_t row = ((size_t)b * S_ + sbase + r) * D_;
                g_V[row + c]     = acc[mt][nt][0] + b0;
                g_V[row + c + 1] = acc[mt][nt][1] + b1;
            }
            if (r + 8 < M) {
                size_t row = ((size_t)b * S_ + sbase + r + 8) * D_;
                g_V[row + c]     = acc[mt][nt][2] + b0;
                g_V[row + c + 1] = acc[mt][nt][3] + b1;
            }
        }
}

// ---------------------------------------------------------------------------
// fp32 FFMA GEMM (precision-critical offset logits), fused tanh(x)*0.5 epilogue
// 64x64x16 tile, 256 threads, 4x4 micro-tile.
// ---------------------------------------------------------------------------
#define BM 64
#define BN 64
#define BK 16

__global__ void gemm_nn_tanh(const float* __restrict__ A, const float* __restrict__ Bm,
                             const float* __restrict__ bias, float* __restrict__ C,
                             int M, int N, int K) {
    __shared__ __align__(16) float As[BK][BM + 4];
    __shared__ __align__(16) float Bs[BK][BN];
    const int tid = threadIdx.x;
    const int tx = tid & 15, ty = tid >> 4;
    const int m0 = blockIdx.x * BM;
    const int n0 = blockIdx.y * BN;

    const int arow = tid >> 2;
    const int acol = (tid & 3) * 4;
    const int brow = tid >> 4;
    const int bcol = (tid & 15) * 4;

    float acc[4][4] = {};

    for (int k0 = 0; k0 < K; k0 += BK) {
        float4 a4 = make_float4(0.f, 0.f, 0.f, 0.f);
        int gm = m0 + arow;
        if (gm < M)
            a4 = *reinterpret_cast<const float4*>(A + (size_t)gm * K + k0 + acol);
        As[acol + 0][arow] = a4.x;
        As[acol + 1][arow] = a4.y;
        As[acol + 2][arow] = a4.z;
        As[acol + 3][arow] = a4.w;

        float4 b4 = make_float4(0.f, 0.f, 0.f, 0.f);
        int gn = n0 + bcol;
        if (gn < N)
            b4 = *reinterpret_cast<const float4*>(Bm + (size_t)(k0 + brow) * N + gn);
        *reinterpret_cast<float4*>(&Bs[brow][bcol]) = b4;

        __syncthreads();
#pragma unroll
        for (int k = 0; k < BK; ++k) {
            float4 av = *reinterpret_cast<const float4*>(&As[k][ty * 4]);
            float4 bv = *reinterpret_cast<const float4*>(&Bs[k][tx * 4]);
            float a[4] = {av.x, av.y, av.z, av.w};
            float bb[4] = {bv.x, bv.y, bv.z, bv.w};
#pragma unroll
            for (int i = 0; i < 4; ++i)
#pragma unroll
                for (int j = 0; j < 4; ++j)
                    acc[i][j] = fmaf(a[i], bb[j], acc[i][j]);
        }
        __syncthreads();
    }

#pragma unroll
    for (int i = 0; i < 4; ++i) {
        int gm = m0 + ty * 4 + i;
        if (gm >= M) continue;
#pragma unroll
        for (int j = 0; j < 4; ++j) {
            int gn = n0 + tx * 4 + j;
            if (gn < N)
                C[(size_t)gm * N + gn] = tanhf(acc[i][j] + bias[gn]) * 0.5f;
        }
    }
}

// ---------------------------------------------------------------------------
// Softmax over 12 (level,point) logits: one thread per (bq, h); in place.
// ---------------------------------------------------------------------------
__global__ void softmax12(float* __restrict__ att) {
    int i = blockIdx.x * blockDim.x + threadIdx.x;
    if (i >= MQ_ * NH_) return;
    float* p = att + (size_t)(i >> 3) * 96 + (i & 7) * 12;
    float v[12], mx = -1e30f;
#pragma unroll
    for (int j = 0; j < 12; ++j) { v[j] = p[j]; mx = fmaxf(mx, v[j]); }
    float s = 0.f;
#pragma unroll
    for (int j = 0; j < 12; ++j) { v[j] = __expf(v[j] - mx); s += v[j]; }
    float inv = 1.f / s;
#pragma unroll
    for (int j = 0; j < 12; ++j) p[j] = v[j] * inv;
}

// ---------------------------------------------------------------------------
// Sampling: one warp per (b, q, h), lane = channel. Offsets pre-tanh'ed,
// weights pre-softmax'ed -> pure gather-accumulate.
// ---------------------------------------------------------------------------
__global__ void sample_kernel(const float* __restrict__ ref) {
    const int warp = (blockIdx.x * blockDim.x + threadIdx.x) >> 5;
    const int lane = threadIdx.x & 31;
    if (warp >= MQ_ * NH_) return;

    const int h  = warp & 7;
    const int bq = warp >> 3;
    const int b  = bq / Q_;

    const float rx = __ldg(ref + (size_t)bq * 2 + 0);
    const float ry = __ldg(ref + (size_t)bq * 2 + 1);

    const float* offp = g_OFF + (size_t)bq * 192 + h * 24;
    const float* attp = g_ATT + (size_t)bq * 96 + h * 12;

    const int Wls[3] = {80, 40, 20};
    const int bas[3] = {0, 6400, 8000};

    const float* Vb = g_V + (size_t)b * S_ * D_ + h * HD_ + lane;

    float acc = 0.f;
#pragma unroll
    for (int l = 0; l < NL_; ++l) {
        const int Wl = Wls[l], base = bas[l];
        const float Wlf = (float)Wl;
#pragma unroll
        for (int p = 0; p < NP_; ++p) {
            const float ox = __ldg(offp + (l * 4 + p) * 2 + 0);
            const float oy = __ldg(offp + (l * 4 + p) * 2 + 1);
            const float w  = __ldg(attp + l * 4 + p);
            const float ix = (rx + ox) * Wlf - 0.5f;
            const float iy = (ry + oy) * Wlf - 0.5f;
            const float x0f = floorf(ix), y0f = floorf(iy);
            const int x0 = (int)x0f, y0 = (int)y0f;
            const float fx = ix - x0f, fy = iy - y0f;
            const float w00 = w * (1.f - fx) * (1.f - fy);
            const float w01 = w * fx * (1.f - fy);
            const float w10 = w * (1.f - fx) * fy;
            const float w11 = w * fx * fy;

            const bool xin0 = (x0 >= 0) && (x0 < Wl);
            const bool xin1 = (x0 + 1 >= 0) && (x0 + 1 < Wl);
            const bool yin0 = (y0 >= 0) && (y0 < Wl);
            const bool yin1 = (y0 + 1 >= 0) && (y0 + 1 < Wl);

            if (xin0 && yin0) acc = fmaf(w00, Vb[(size_t)(base + y0 * Wl + x0) * D_], acc);
            if (xin1 && yin0) acc = fmaf(w01, Vb[(size_t)(base + y0 * Wl + x0 + 1) * D_], acc);
            if (xin0 && yin1) acc = fmaf(w10, Vb[(size_t)(base + (y0 + 1) * Wl + x0) * D_], acc);
            if (xin1 && yin1) acc = fmaf(w11, Vb[(size_t)(base + (y0 + 1) * Wl + x0 + 1) * D_], acc);
        }
    }

    g_MID[(size_t)bq * D_ + h * HD_ + lane] = acc;
}

// ---------------------------------------------------------------------------
// Launch
// ---------------------------------------------------------------------------
extern "C" void kernel_launch(void* const* d_in, const int* in_sizes, int n_in,
                              void* d_out, int out_size) {
    const float* query = (const float*)d_in[0];
    const float* feat0 = (const float*)d_in[1];
    const float* feat1 = (const float*)d_in[2];
    const float* feat2 = (const float*)d_in[3];
    const float* refp  = (const float*)d_in[4];
    const float* W_off = (const float*)d_in[5];
    const float* b_off = (const float*)d_in[6];
    const float* W_att = (const float*)d_in[7];
    const float* b_att = (const float*)d_in[8];
    const float* W_val = (const float*)d_in[9];
    const float* b_val = (const float*)d_in[10];
    const float* W_out = (const float*)d_in[11];
    const float* b_out = (const float*)d_in[12];
    float* out = (float*)d_out;

    float* pOFF; cudaGetSymbolAddress((void**)&pOFF, g_OFF);
    float* pATT; cudaGetSymbolAddress((void**)&pATT, g_ATT);
    float* pMID; cudaGetSymbolAddress((void**)&pMID, g_MID);

    dim3 blk(256);

    // 1) value projection per level (tf32 tensor cores)
    gemm_tn_tf32<<<dim3(50, 4, B_), blk>>>(feat0, W_val, b_val, 6400, 0);
    gemm_tn_tf32<<<dim3(13, 4, B_), blk>>>(feat1, W_val, b_val, 1600, 6400);
    gemm_tn_tf32<<<dim3( 4, 4, B_), blk>>>(feat2, W_val, b_val,  400, 8000);

    // 2) offset logits (fp32 FFMA, fused tanh*0.5)
    gemm_nn_tanh<<<dim3(MQ_ / BM, 3), blk>>>(query, W_off, b_off, pOFF, MQ_, 192, D_);

    // 3) attention logits (tf32) + softmax
    gemm_nn_tf32<<<dim3((MQ_ + 127) / 128, 2), blk>>>(query, W_att, b_att, pATT, MQ_, 96, D_);
    softmax12<<<(MQ_ * NH_ + 255) / 256, 256>>>(pATT);

    // 4) bilinear sampling -> MID
    {
        int nwarps = MQ_ * NH_;
        int blocks = (nwarps * 32 + 255) / 256;
        sample_kernel<<<blocks, 256>>>(refp);
    }

    // 5) output projection (tf32)
    gemm_nn_tf32<<<dim3((MQ_ + 127) / 128, 4), blk>>>(pMID, W_out, b_out, out, MQ_, D_, D_);
}

// round 6
// speedup vs baseline: 2.1024x; 1.3362x over previous
#include <cuda_runtime.h>
#include <cstdint>

// ---------------------------------------------------------------------------
// MultiScaleDETR deformable attention.
// B=4, Q=8400, D=256, nH=8, hd=32, L=3 (80x80,40x40,20x20), P=4.
// tf32 tensor-core GEMMs for value/attn/output; 3xTF32 split-precision
// tensor-core GEMM for offsets (fp32-grade precision on tensor pipe).
// ---------------------------------------------------------------------------

#define B_    4
#define Q_    8400
#define D_    256
#define NH_   8
#define HD_   32
#define NL_   3
#define NP_   4
#define S_    8400
#define MQ_   (B_ * Q_)      // 33600

__device__ float g_V  [B_ * S_ * D_];   // value projection [b][s][d]
__device__ float g_OFF[MQ_ * 192];      // tanh(offset_logit)*0.5
__device__ float g_ATT[MQ_ * 96];       // attn logits -> softmax'ed in place
__device__ float g_MID[MQ_ * D_];       // attention output pre-W_out

// ---------------------------------------------------------------------------
// tf32 helpers
// ---------------------------------------------------------------------------
__device__ __forceinline__ uint32_t f2tf32(float f) {
    uint32_t u;
    asm("cvt.rna.tf32.f32 %0, %1;" : "=r"(u) : "f"(f));
    return u;
}

__device__ __forceinline__ void mma_tf32(float* d, const uint32_t* a, const uint32_t* b) {
    asm volatile(
        "mma.sync.aligned.m16n8k8.row.col.f32.tf32.tf32.f32 "
        "{%0,%1,%2,%3}, {%4,%5,%6,%7}, {%8,%9}, {%0,%1,%2,%3};\n"
        : "+f"(d[0]), "+f"(d[1]), "+f"(d[2]), "+f"(d[3])
        : "r"(a[0]), "r"(a[1]), "r"(a[2]), "r"(a[3]), "r"(b[0]), "r"(b[1]));
}

// ---------------------------------------------------------------------------
// tf32 GEMM (NN): C[M,N] = A[M,K](row) @ B[K,N](row) + bias
// 128x64x16 tile, 256 threads = 8 warps (4m x 2n), warp tile 32x32.
// ---------------------------------------------------------------------------
__global__ void gemm_nn_tf32(const float* __restrict__ A, const float* __restrict__ Bm,
                             const float* __restrict__ bias, float* __restrict__ C,
                             int M, int N, int K) {
    __shared__ __align__(16) uint32_t As[128][20];
    __shared__ __align__(16) uint32_t Bs[16][72];
    const int tid  = threadIdx.x;
    const int lane = tid & 31;
    const int warp = tid >> 5;
    const int g  = lane >> 2, t4 = lane & 3;
    const int wm = warp >> 1, wn = warp & 1;
    const int m0 = blockIdx.x * 128, n0 = blockIdx.y * 64;

    float acc[2][4][4] = {};

    for (int k0 = 0; k0 < K; k0 += 16) {
#pragma unroll
        for (int p = 0; p < 2; ++p) {
            int m  = p * 64 + (tid >> 2);
            int kk = (tid & 3) * 4;
            float4 a4 = make_float4(0.f, 0.f, 0.f, 0.f);
            int gm = m0 + m;
            if (gm < M) a4 = *reinterpret_cast<const float4*>(A + (size_t)gm * K + k0 + kk);
            uint4 u;
            u.x = f2tf32(a4.x); u.y = f2tf32(a4.y); u.z = f2tf32(a4.z); u.w = f2tf32(a4.w);
            *reinterpret_cast<uint4*>(&As[m][kk]) = u;
        }
        {
            int kr = tid >> 4, nn = (tid & 15) * 4;
            float4 b4 = make_float4(0.f, 0.f, 0.f, 0.f);
            if (n0 + nn < N)
                b4 = *reinterpret_cast<const float4*>(Bm + (size_t)(k0 + kr) * N + n0 + nn);
            uint4 u;
            u.x = f2tf32(b4.x); u.y = f2tf32(b4.y); u.z = f2tf32(b4.z); u.w = f2tf32(b4.w);
            *reinterpret_cast<uint4*>(&Bs[kr][nn]) = u;
        }
        __syncthreads();
#pragma unroll
        for (int ks = 0; ks < 2; ++ks) {
            const int kb = ks * 8;
            uint32_t af[2][4], bf[4][2];
#pragma unroll
            for (int mt = 0; mt < 2; ++mt) {
                int rb = wm * 32 + mt * 16;
                af[mt][0] = As[rb + g    ][kb + t4    ];
                af[mt][1] = As[rb + g + 8][kb + t4    ];
                af[mt][2] = As[rb + g    ][kb + t4 + 4];
                af[mt][3] = As[rb + g + 8][kb + t4 + 4];
            }
#pragma unroll
            for (int nt = 0; nt < 4; ++nt) {
                int cb = wn * 32 + nt * 8;
                bf[nt][0] = Bs[kb + t4    ][cb + g];
                bf[nt][1] = Bs[kb + t4 + 4][cb + g];
            }
#pragma unroll
            for (int mt = 0; mt < 2; ++mt)
#pragma unroll
                for (int nt = 0; nt < 4; ++nt)
                    mma_tf32(acc[mt][nt], af[mt], bf[nt]);
        }
        __syncthreads();
    }

#pragma unroll
    for (int mt = 0; mt < 2; ++mt)
#pragma unroll
        for (int nt = 0; nt < 4; ++nt) {
            int r = m0 + wm * 32 + mt * 16 + g;
            int c = n0 + wn * 32 + nt * 8 + t4 * 2;
            if (c < N) {
                float b0 = bias[c], b1 = bias[c + 1];
                if (r < M) {
                    C[(size_t)r * N + c]     = acc[mt][nt][0] + b0;
                    C[(size_t)r * N + c + 1] = acc[mt][nt][1] + b1;
                }
                if (r + 8 < M) {
                    C[(size_t)(r + 8) * N + c]     = acc[mt][nt][2] + b0;
                    C[(size_t)(r + 8) * N + c + 1] = acc[mt][nt][3] + b1;
                }
            }
        }
}

// ---------------------------------------------------------------------------
// 3xTF32 GEMM (NN) with tanh(x)*0.5 epilogue — fp32-grade offsets on HMMA.
// a = hi + lo (tf32 splits); acc += hi*hi + hi*lo + lo*hi.
// ---------------------------------------------------------------------------
__global__ void gemm_nn_tanh_3x(const float* __restrict__ A, const float* __restrict__ Bm,
                                const float* __restrict__ bias, float* __restrict__ C,
                                int M, int N, int K) {
    __shared__ __align__(16) uint32_t AsH[128][20];
    __shared__ __align__(16) uint32_t AsL[128][20];
    __shared__ __align__(16) uint32_t BsH[16][72];
    __shared__ __align__(16) uint32_t BsL[16][72];
    const int tid  = threadIdx.x;
    const int lane = tid & 31;
    const int warp = tid >> 5;
    const int g  = lane >> 2, t4 = lane & 3;
    const int wm = warp >> 1, wn = warp & 1;
    const int m0 = blockIdx.x * 128, n0 = blockIdx.y * 64;

    float acc[2][4][4] = {};

    for (int k0 = 0; k0 < K; k0 += 16) {
#pragma unroll
        for (int p = 0; p < 2; ++p) {
            int m  = p * 64 + (tid >> 2);
            int kk = (tid & 3) * 4;
            float4 a4 = make_float4(0.f, 0.f, 0.f, 0.f);
            int gm = m0 + m;
            if (gm < M) a4 = *reinterpret_cast<const float4*>(A + (size_t)gm * K + k0 + kk);
            uint4 hi, lo;
            hi.x = f2tf32(a4.x); lo.x = f2tf32(a4.x - __uint_as_float(hi.x));
            hi.y = f2tf32(a4.y); lo.y = f2tf32(a4.y - __uint_as_float(hi.y));
            hi.z = f2tf32(a4.z); lo.z = f2tf32(a4.z - __uint_as_float(hi.z));
            hi.w = f2tf32(a4.w); lo.w = f2tf32(a4.w - __uint_as_float(hi.w));
            *reinterpret_cast<uint4*>(&AsH[m][kk]) = hi;
            *reinterpret_cast<uint4*>(&AsL[m][kk]) = lo;
        }
        {
            int kr = tid >> 4, nn = (tid & 15) * 4;
            float4 b4 = make_float4(0.f, 0.f, 0.f, 0.f);
            if (n0 + nn < N)
                b4 = *reinterpret_cast<const float4*>(Bm + (size_t)(k0 + kr) * N + n0 + nn);
            uint4 hi, lo;
            hi.x = f2tf32(b4.x); lo.x = f2tf32(b4.x - __uint_as_float(hi.x));
            hi.y = f2tf32(b4.y); lo.y = f2tf32(b4.y - __uint_as_float(hi.y));
            hi.z = f2tf32(b4.z); lo.z = f2tf32(b4.z - __uint_as_float(hi.z));
            hi.w = f2tf32(b4.w); lo.w = f2tf32(b4.w - __uint_as_float(hi.w));
            *reinterpret_cast<uint4*>(&BsH[kr][nn]) = hi;
            *reinterpret_cast<uint4*>(&BsL[kr][nn]) = lo;
        }
        __syncthreads();
#pragma unroll
        for (int ks = 0; ks < 2; ++ks) {
            const int kb = ks * 8;
            uint32_t afH[2][4], afL[2][4], bfH[4][2], bfL[4][2];
#pragma unroll
            for (int mt = 0; mt < 2; ++mt) {
                int rb = wm * 32 + mt * 16;
                afH[mt][0] = AsH[rb + g    ][kb + t4    ];
                afH[mt][1] = AsH[rb + g + 8][kb + t4    ];
                afH[mt][2] = AsH[rb + g    ][kb + t4 + 4];
                afH[mt][3] = AsH[rb + g + 8][kb + t4 + 4];
                afL[mt][0] = AsL[rb + g    ][kb + t4    ];
                afL[mt][1] = AsL[rb + g + 8][kb + t4    ];
                afL[mt][2] = AsL[rb + g    ][kb + t4 + 4];
                afL[mt][3] = AsL[rb + g + 8][kb + t4 + 4];
            }
#pragma unroll
            for (int nt = 0; nt < 4; ++nt) {
                int cb = wn * 32 + nt * 8;
                bfH[nt][0] = BsH[kb + t4    ][cb + g];
                bfH[nt][1] = BsH[kb + t4 + 4][cb + g];
                bfL[nt][0] = BsL[kb + t4    ][cb + g];
                bfL[nt][1] = BsL[kb + t4 + 4][cb + g];
            }
#pragma unroll
            for (int mt = 0; mt < 2; ++mt)
#pragma unroll
                for (int nt = 0; nt < 4; ++nt) {
                    mma_tf32(acc[mt][nt], afH[mt], bfL[nt]);
                    mma_tf32(acc[mt][nt], afL[mt], bfH[nt]);
                    mma_tf32(acc[mt][nt], afH[mt], bfH[nt]);
                }
        }
        __syncthreads();
    }

#pragma unroll
    for (int mt = 0; mt < 2; ++mt)
#pragma unroll
        for (int nt = 0; nt < 4; ++nt) {
            int r = m0 + wm * 32 + mt * 16 + g;
            int c = n0 + wn * 32 + nt * 8 + t4 * 2;
            if (c < N) {
                float b0 = bias[c], b1 = bias[c + 1];
                if (r < M) {
                    C[(size_t)r * N + c]     = tanhf(acc[mt][nt][0] + b0) * 0.5f;
                    C[(size_t)r * N + c + 1] = tanhf(acc[mt][nt][1] + b1) * 0.5f;
                }
                if (r + 8 < M) {
                    C[(size_t)(r + 8) * N + c]     = tanhf(acc[mt][nt][2] + b0) * 0.5f;
                    C[(size_t)(r + 8) * N + c + 1] = tanhf(acc[mt][nt][3] + b1) * 0.5f;
                }
            }
        }
}

// ---------------------------------------------------------------------------
// tf32 GEMM (TN) for value projection.
// ---------------------------------------------------------------------------
__global__ void gemm_tn_tf32(const float* __restrict__ feat, const float* __restrict__ W,
                             const float* __restrict__ bias, int M /*HW*/, int sbase) {
    __shared__ __align__(16) uint32_t As[16][136];
    __shared__ __align__(16) uint32_t Bs[16][72];
    const int tid  = threadIdx.x;
    const int lane = tid & 31;
    const int warp = tid >> 5;
    const int g  = lane >> 2, t4 = lane & 3;
    const int wm = warp >> 1, wn = warp & 1;
    const int m0 = blockIdx.x * 128, n0 = blockIdx.y * 64;
    const int b  = blockIdx.z;
    const int K = D_, N = D_;

    const float* A = feat + (size_t)b * K * M;

    float acc[2][4][4] = {};

    for (int k0 = 0; k0 < K; k0 += 16) {
#pragma unroll
        for (int p = 0; p < 2; ++p) {
            int m = p * 64 + (tid & 15) * 4;
            int k = tid >> 4;
            float4 a4 = make_float4(0.f, 0.f, 0.f, 0.f);
            if (m0 + m < M)
                a4 = *reinterpret_cast<const float4*>(A + (size_t)(k0 + k) * M + m0 + m);
            uint4 u;
            u.x = f2tf32(a4.x); u.y = f2tf32(a4.y); u.z = f2tf32(a4.z); u.w = f2tf32(a4.w);
            *reinterpret_cast<uint4*>(&As[k][m]) = u;
        }
        {
            int kr = tid >> 4, nn = (tid & 15) * 4;
            float4 b4 = *reinterpret_cast<const float4*>(W + (size_t)(k0 + kr) * N + n0 + nn);
            uint4 u;
            u.x = f2tf32(b4.x); u.y = f2tf32(b4.y); u.z = f2tf32(b4.z); u.w = f2tf32(b4.w);
            *reinterpret_cast<uint4*>(&Bs[kr][nn]) = u;
        }
        __syncthreads();
#pragma unroll
        for (int ks = 0; ks < 2; ++ks) {
            const int kb = ks * 8;
            uint32_t af[2][4], bf[4][2];
#pragma unroll
            for (int mt = 0; mt < 2; ++mt) {
                int rb = wm * 32 + mt * 16;
                af[mt][0] = As[kb + t4    ][rb + g    ];
                af[mt][1] = As[kb + t4    ][rb + g + 8];
                af[mt][2] = As[kb + t4 + 4][rb + g    ];
                af[mt][3] = As[kb + t4 + 4][rb + g + 8];
            }
#pragma unroll
            for (int nt = 0; nt < 4; ++nt) {
                int cb = wn * 32 + nt * 8;
                bf[nt][0] = Bs[kb + t4    ][cb + g];
                bf[nt][1] = Bs[kb + t4 + 4][cb + g];
            }
#pragma unroll
            for (int mt = 0; mt < 2; ++mt)
#pragma unroll
                for (int nt = 0; nt < 4; ++nt)
                    mma_tf32(acc[mt][nt], af[mt], bf[nt]);
        }
        __syncthreads();
    }

#pragma unroll
    for (int mt = 0; mt < 2; ++mt)
#pragma unroll
        for (int nt = 0; nt < 4; ++nt) {
            int r = m0 + wm * 32 + mt * 16 + g;
            int c = n0 + wn * 32 + nt * 8 + t4 * 2;
            float b0 = bias[c], b1 = bias[c + 1];
            if (r < M) {
                size_t row = ((size_t)b * S_ + sbase + r) * D_;
                g_V[row + c]     = acc[mt][nt][0] + b0;
                g_V[row + c + 1] = acc[mt][nt][1] + b1;
            }
            if (r + 8 < M) {
                size_t row = ((size_t)b * S_ + sbase + r + 8) * D_;
                g_V[row + c]     = acc[mt][nt][2] + b0;
                g_V[row + c + 1] = acc[mt][nt][3] + b1;
            }
        }
}

// ---------------------------------------------------------------------------
// Softmax over 12 (level,point) logits: one thread per (bq, h); in place.
// ---------------------------------------------------------------------------
__global__ void softmax12(float* __restrict__ att) {
    int i = blockIdx.x * blockDim.x + threadIdx.x;
    if (i >= MQ_ * NH_) return;
    float* p = att + (size_t)(i >> 3) * 96 + (i & 7) * 12;
    float v[12], mx = -1e30f;
#pragma unroll
    for (int j = 0; j < 12; ++j) { v[j] = p[j]; mx = fmaxf(mx, v[j]); }
    float s = 0.f;
#pragma unroll
    for (int j = 0; j < 12; ++j) { v[j] = __expf(v[j] - mx); s += v[j]; }
    float inv = 1.f / s;
#pragma unroll
    for (int j = 0; j < 12; ++j) p[j] = v[j] * inv;
}

// ---------------------------------------------------------------------------
// Sampling v2: one warp per (b,q). 8 lanes per head (float4 channels),
// 4 heads per pass, 2 passes. 4x fewer LDG / scalar instructions vs v1.
// ---------------------------------------------------------------------------
__global__ void sample_kernel(const float* __restrict__ ref) {
    const int warp = (blockIdx.x * blockDim.x + threadIdx.x) >> 5;
    const int lane = threadIdx.x & 31;
    if (warp >= MQ_) return;

    const int bq  = warp;
    const int b   = bq / Q_;
    const int grp = lane >> 3;          // head group 0..3
    const int cl  = (lane & 7) * 4;     // channel offset within head

    const float rx = __ldg(ref + (size_t)bq * 2 + 0);
    const float ry = __ldg(ref + (size_t)bq * 2 + 1);

    const int Wls[3] = {80, 40, 20};
    const int bas[3] = {0, 6400, 8000};

    const float* Vbase = g_V + (size_t)b * S_ * D_;

#pragma unroll
    for (int pass = 0; pass < 2; ++pass) {
        const int h = grp + pass * 4;
        const float* offp = g_OFF + (size_t)bq * 192 + h * 24;
        const float* attp = g_ATT + (size_t)bq * 96 + h * 12;
        const float* Vb   = Vbase + h * HD_ + cl;

        float4 acc = make_float4(0.f, 0.f, 0.f, 0.f);
#pragma unroll
        for (int l = 0; l < NL_; ++l) {
            const int Wl = Wls[l], base = bas[l];
            const float Wlf = (float)Wl;
#pragma unroll
            for (int p = 0; p < NP_; ++p) {
                const float ox = __ldg(offp + (l * 4 + p) * 2 + 0);
                const float oy = __ldg(offp + (l * 4 + p) * 2 + 1);
                const float w  = __ldg(attp + l * 4 + p);
                const float ix = (rx + ox) * Wlf - 0.5f;
                const float iy = (ry + oy) * Wlf - 0.5f;
                const float x0f = floorf(ix), y0f = floorf(iy);
                const int x0 = (int)x0f, y0 = (int)y0f;
                const float fx = ix - x0f, fy = iy - y0f;
                const float w00 = w * (1.f - fx) * (1.f - fy);
                const float w01 = w * fx * (1.f - fy);
                const float w10 = w * (1.f - fx) * fy;
                const float w11 = w * fx * fy;

                const bool xin0 = (x0 >= 0) && (x0 < Wl);
                const bool xin1 = (x0 + 1 >= 0) && (x0 + 1 < Wl);
                const bool yin0 = (y0 >= 0) && (y0 < Wl);
                const bool yin1 = (y0 + 1 >= 0) && (y0 + 1 < Wl);

                if (xin0 && yin0) {
                    float4 v = *reinterpret_cast<const float4*>(Vb + (size_t)(base + y0 * Wl + x0) * D_);
                    acc.x = fmaf(w00, v.x, acc.x); acc.y = fmaf(w00, v.y, acc.y);
                    acc.z = fmaf(w00, v.z, acc.z); acc.w = fmaf(w00, v.w, acc.w);
                }
                if (xin1 && yin0) {
                    float4 v = *reinterpret_cast<const float4*>(Vb + (size_t)(base + y0 * Wl + x0 + 1) * D_);
                    acc.x = fmaf(w01, v.x, acc.x); acc.y = fmaf(w01, v.y, acc.y);
                    acc.z = fmaf(w01, v.z, acc.z); acc.w = fmaf(w01, v.w, acc.w);
                }
                if (xin0 && yin1) {
                    float4 v = *reinterpret_cast<const float4*>(Vb + (size_t)(base + (y0 + 1) * Wl + x0) * D_);
                    acc.x = fmaf(w10, v.x, acc.x); acc.y = fmaf(w10, v.y, acc.y);
                    acc.z = fmaf(w10, v.z, acc.z); acc.w = fmaf(w10, v.w, acc.w);
                }
                if (xin1 && yin1) {
                    float4 v = *reinterpret_cast<const float4*>(Vb + (size_t)(base + (y0 + 1) * Wl + x0 + 1) * D_);
                    acc.x = fmaf(w11, v.x, acc.x); acc.y = fmaf(w11, v.y, acc.y);
                    acc.z = fmaf(w11, v.z, acc.z); acc.w = fmaf(w11, v.w, acc.w);
                }
            }
        }
        *reinterpret_cast<float4*>(g_MID + (size_t)bq * D_ + h * HD_ + cl) = acc;
    }
}

// ---------------------------------------------------------------------------
// Launch
// ---------------------------------------------------------------------------
extern "C" void kernel_launch(void* const* d_in, const int* in_sizes, int n_in,
                              void* d_out, int out_size) {
    const float* query = (const float*)d_in[0];
    const float* feat0 = (const float*)d_in[1];
    const float* feat1 = (const float*)d_in[2];
    const float* feat2 = (const float*)d_in[3];
    const float* refp  = (const float*)d_in[4];
    const float* W_off = (const float*)d_in[5];
    const float* b_off = (const float*)d_in[6];
    const float* W_att = (const float*)d_in[7];
    const float* b_att = (const float*)d_in[8];
    const float* W_val = (const float*)d_in[9];
    const float* b_val = (const float*)d_in[10];
    const float* W_out = (const float*)d_in[11];
    const float* b_out = (const float*)d_in[12];
    float* out = (float*)d_out;

    float* pOFF; cudaGetSymbolAddress((void**)&pOFF, g_OFF);
    float* pATT; cudaGetSymbolAddress((void**)&pATT, g_ATT);
    float* pMID; cudaGetSymbolAddress((void**)&pMID, g_MID);

    dim3 blk(256);

    // 1) value projection per level (tf32 tensor cores)
    gemm_tn_tf32<<<dim3(50, 4, B_), blk>>>(feat0, W_val, b_val, 6400, 0);
    gemm_tn_tf32<<<dim3(13, 4, B_), blk>>>(feat1, W_val, b_val, 1600, 6400);
    gemm_tn_tf32<<<dim3( 4, 4, B_), blk>>>(feat2, W_val, b_val,  400, 8000);

    // 2) offset logits (3xTF32 tensor cores, fused tanh*0.5)
    gemm_nn_tanh_3x<<<dim3((MQ_ + 127) / 128, 3), blk>>>(query, W_off, b_off, pOFF, MQ_, 192, D_);

    // 3) attention logits (tf32) + softmax
    gemm_nn_tf32<<<dim3((MQ_ + 127) / 128, 2), blk>>>(query, W_att, b_att, pATT, MQ_, 96, D_);
    softmax12<<<(MQ_ * NH_ + 255) / 256, 256>>>(pATT);

    // 4) bilinear sampling -> MID (warp per (b,q), float4 lanes)
    sample_kernel<<<(MQ_ + 7) / 8, 256>>>(refp);

    // 5) output projection (tf32)
    gemm_nn_tf32<<<dim3((MQ_ + 127) / 128, 4), blk>>>(pMID, W_out, b_out, out, MQ_, D_, D_);
}

// round 7
// speedup vs baseline: 2.1982x; 1.0456x over previous
#include <cuda_runtime.h>
#include <cuda_fp16.h>
#include <cstdint>

// ---------------------------------------------------------------------------
// MultiScaleDETR deformable attention.
// B=4, Q=8400, D=256, nH=8, hd=32, L=3 (80x80,40x40,20x20), P=4.
// tf32 tensor-core GEMMs; 3xTF32 split for offsets; V stored fp16 to halve
// the L2-bound gather traffic in the sampler.
// ---------------------------------------------------------------------------

#define B_    4
#define Q_    8400
#define D_    256
#define NH_   8
#define HD_   32
#define NL_   3
#define NP_   4
#define S_    8400
#define MQ_   (B_ * Q_)      // 33600

__device__ __half g_Vh [B_ * S_ * D_];  // value projection [b][s][d], fp16
__device__ float  g_OFF[MQ_ * 192];     // tanh(offset_logit)*0.5
__device__ float  g_ATT[MQ_ * 96];      // attn logits -> softmax'ed in place
__device__ float  g_MID[MQ_ * D_];      // attention output pre-W_out

// ---------------------------------------------------------------------------
// tf32 helpers
// ---------------------------------------------------------------------------
__device__ __forceinline__ uint32_t f2tf32(float f) {
    uint32_t u;
    asm("cvt.rna.tf32.f32 %0, %1;" : "=r"(u) : "f"(f));
    return u;
}

__device__ __forceinline__ void mma_tf32(float* d, const uint32_t* a, const uint32_t* b) {
    asm volatile(
        "mma.sync.aligned.m16n8k8.row.col.f32.tf32.tf32.f32 "
        "{%0,%1,%2,%3}, {%4,%5,%6,%7}, {%8,%9}, {%0,%1,%2,%3};\n"
        : "+f"(d[0]), "+f"(d[1]), "+f"(d[2]), "+f"(d[3])
        : "r"(a[0]), "r"(a[1]), "r"(a[2]), "r"(a[3]), "r"(b[0]), "r"(b[1]));
}

// ---------------------------------------------------------------------------
// tf32 GEMM (NN): C[M,N] = A[M,K](row) @ B[K,N](row) + bias
// 128x64x16 tile, 256 threads = 8 warps (4m x 2n), warp tile 32x32.
// ---------------------------------------------------------------------------
__global__ void gemm_nn_tf32(const float* __restrict__ A, const float* __restrict__ Bm,
                             const float* __restrict__ bias, float* __restrict__ C,
                             int M, int N, int K) {
    __shared__ __align__(16) uint32_t As[128][20];
    __shared__ __align__(16) uint32_t Bs[16][72];
    const int tid  = threadIdx.x;
    const int lane = tid & 31;
    const int warp = tid >> 5;
    const int g  = lane >> 2, t4 = lane & 3;
    const int wm = warp >> 1, wn = warp & 1;
    const int m0 = blockIdx.x * 128, n0 = blockIdx.y * 64;

    float acc[2][4][4] = {};

    for (int k0 = 0; k0 < K; k0 += 16) {
#pragma unroll
        for (int p = 0; p < 2; ++p) {
            int m  = p * 64 + (tid >> 2);
            int kk = (tid & 3) * 4;
            float4 a4 = make_float4(0.f, 0.f, 0.f, 0.f);
            int gm = m0 + m;
            if (gm < M) a4 = *reinterpret_cast<const float4*>(A + (size_t)gm * K + k0 + kk);
            uint4 u;
            u.x = f2tf32(a4.x); u.y = f2tf32(a4.y); u.z = f2tf32(a4.z); u.w = f2tf32(a4.w);
            *reinterpret_cast<uint4*>(&As[m][kk]) = u;
        }
        {
            int kr = tid >> 4, nn = (tid & 15) * 4;
            float4 b4 = make_float4(0.f, 0.f, 0.f, 0.f);
            if (n0 + nn < N)
                b4 = *reinterpret_cast<const float4*>(Bm + (size_t)(k0 + kr) * N + n0 + nn);
            uint4 u;
            u.x = f2tf32(b4.x); u.y = f2tf32(b4.y); u.z = f2tf32(b4.z); u.w = f2tf32(b4.w);
            *reinterpret_cast<uint4*>(&Bs[kr][nn]) = u;
        }
        __syncthreads();
#pragma unroll
        for (int ks = 0; ks < 2; ++ks) {
            const int kb = ks * 8;
            uint32_t af[2][4], bf[4][2];
#pragma unroll
            for (int mt = 0; mt < 2; ++mt) {
                int rb = wm * 32 + mt * 16;
                af[mt][0] = As[rb + g    ][kb + t4    ];
                af[mt][1] = As[rb + g + 8][kb + t4    ];
                af[mt][2] = As[rb + g    ][kb + t4 + 4];
                af[mt][3] = As[rb + g + 8][kb + t4 + 4];
            }
#pragma unroll
            for (int nt = 0; nt < 4; ++nt) {
                int cb = wn * 32 + nt * 8;
                bf[nt][0] = Bs[kb + t4    ][cb + g];
                bf[nt][1] = Bs[kb + t4 + 4][cb + g];
            }
#pragma unroll
            for (int mt = 0; mt < 2; ++mt)
#pragma unroll
                for (int nt = 0; nt < 4; ++nt)
                    mma_tf32(acc[mt][nt], af[mt], bf[nt]);
        }
        __syncthreads();
    }

#pragma unroll
    for (int mt = 0; mt < 2; ++mt)
#pragma unroll
        for (int nt = 0; nt < 4; ++nt) {
            int r = m0 + wm * 32 + mt * 16 + g;
            int c = n0 + wn * 32 + nt * 8 + t4 * 2;
            if (c < N) {
                float b0 = bias[c], b1 = bias[c + 1];
                if (r < M) {
                    C[(size_t)r * N + c]     = acc[mt][nt][0] + b0;
                    C[(size_t)r * N + c + 1] = acc[mt][nt][1] + b1;
                }
                if (r + 8 < M) {
                    C[(size_t)(r + 8) * N + c]     = acc[mt][nt][2] + b0;
                    C[(size_t)(r + 8) * N + c + 1] = acc[mt][nt][3] + b1;
                }
            }
        }
}

// ---------------------------------------------------------------------------
// 3xTF32 GEMM (NN) with tanh(x)*0.5 epilogue.
// Pass-ordered mainloop: H*L sweep, L*H sweep, H*H sweep -> 8 independent
// mmas between accumulator reuses (was 3 dependent back-to-back).
// ---------------------------------------------------------------------------
__global__ void gemm_nn_tanh_3x(const float* __restrict__ A, const float* __restrict__ Bm,
                                const float* __restrict__ bias, float* __restrict__ C,
                                int M, int N, int K) {
    __shared__ __align__(16) uint32_t AsH[128][20];
    __shared__ __align__(16) uint32_t AsL[128][20];
    __shared__ __align__(16) uint32_t BsH[16][72];
    __shared__ __align__(16) uint32_t BsL[16][72];
    const int tid  = threadIdx.x;
    const int lane = tid & 31;
    const int warp = tid >> 5;
    const int g  = lane >> 2, t4 = lane & 3;
    const int wm = warp >> 1, wn = warp & 1;
    const int m0 = blockIdx.x * 128, n0 = blockIdx.y * 64;

    float acc[2][4][4] = {};

    for (int k0 = 0; k0 < K; k0 += 16) {
#pragma unroll
        for (int p = 0; p < 2; ++p) {
            int m  = p * 64 + (tid >> 2);
            int kk = (tid & 3) * 4;
            float4 a4 = make_float4(0.f, 0.f, 0.f, 0.f);
            int gm = m0 + m;
            if (gm < M) a4 = *reinterpret_cast<const float4*>(A + (size_t)gm * K + k0 + kk);
            uint4 hi, lo;
            hi.x = f2tf32(a4.x); lo.x = f2tf32(a4.x - __uint_as_float(hi.x));
            hi.y = f2tf32(a4.y); lo.y = f2tf32(a4.y - __uint_as_float(hi.y));
            hi.z = f2tf32(a4.z); lo.z = f2tf32(a4.z - __uint_as_float(hi.z));
            hi.w = f2tf32(a4.w); lo.w = f2tf32(a4.w - __uint_as_float(hi.w));
            *reinterpret_cast<uint4*>(&AsH[m][kk]) = hi;
            *reinterpret_cast<uint4*>(&AsL[m][kk]) = lo;
        }
        {
            int kr = tid >> 4, nn = (tid & 15) * 4;
            float4 b4 = make_float4(0.f, 0.f, 0.f, 0.f);
            if (n0 + nn < N)
                b4 = *reinterpret_cast<const float4*>(Bm + (size_t)(k0 + kr) * N + n0 + nn);
            uint4 hi, lo;
            hi.x = f2tf32(b4.x); lo.x = f2tf32(b4.x - __uint_as_float(hi.x));
            hi.y = f2tf32(b4.y); lo.y = f2tf32(b4.y - __uint_as_float(hi.y));
            hi.z = f2tf32(b4.z); lo.z = f2tf32(b4.z - __uint_as_float(hi.z));
            hi.w = f2tf32(b4.w); lo.w = f2tf32(b4.w - __uint_as_float(hi.w));
            *reinterpret_cast<uint4*>(&BsH[kr][nn]) = hi;
            *reinterpret_cast<uint4*>(&BsL[kr][nn]) = lo;
        }
        __syncthreads();
#pragma unroll
        for (int ks = 0; ks < 2; ++ks) {
            const int kb = ks * 8;
            uint32_t afH[2][4], afL[2][4], bfH[4][2], bfL[4][2];
#pragma unroll
            for (int mt = 0; mt < 2; ++mt) {
                int rb = wm * 32 + mt * 16;
                afH[mt][0] = AsH[rb + g    ][kb + t4    ];
                afH[mt][1] = AsH[rb + g + 8][kb + t4    ];
                afH[mt][2] = AsH[rb + g    ][kb + t4 + 4];
                afH[mt][3] = AsH[rb + g + 8][kb + t4 + 4];
                afL[mt][0] = AsL[rb + g    ][kb + t4    ];
                afL[mt][1] = AsL[rb + g + 8][kb + t4    ];
                afL[mt][2] = AsL[rb + g    ][kb + t4 + 4];
                afL[mt][3] = AsL[rb + g + 8][kb + t4 + 4];
            }
#pragma unroll
            for (int nt = 0; nt < 4; ++nt) {
                int cb = wn * 32 + nt * 8;
                bfH[nt][0] = BsH[kb + t4    ][cb + g];
                bfH[nt][1] = BsH[kb + t4 + 4][cb + g];
                bfL[nt][0] = BsL[kb + t4    ][cb + g];
                bfL[nt][1] = BsL[kb + t4 + 4][cb + g];
            }
            // pass 1: H * L  (8 independent mmas)
#pragma unroll
            for (int mt = 0; mt < 2; ++mt)
#pragma unroll
                for (int nt = 0; nt < 4; ++nt)
                    mma_tf32(acc[mt][nt], afH[mt], bfL[nt]);
            // pass 2: L * H
#pragma unroll
            for (int mt = 0; mt < 2; ++mt)
#pragma unroll
                for (int nt = 0; nt < 4; ++nt)
                    mma_tf32(acc[mt][nt], afL[mt], bfH[nt]);
            // pass 3: H * H
#pragma unroll
            for (int mt = 0; mt < 2; ++mt)
#pragma unroll
                for (int nt = 0; nt < 4; ++nt)
                    mma_tf32(acc[mt][nt], afH[mt], bfH[nt]);
        }
        __syncthreads();
    }

#pragma unroll
    for (int mt = 0; mt < 2; ++mt)
#pragma unroll
        for (int nt = 0; nt < 4; ++nt) {
            int r = m0 + wm * 32 + mt * 16 + g;
            int c = n0 + wn * 32 + nt * 8 + t4 * 2;
            if (c < N) {
                float b0 = bias[c], b1 = bias[c + 1];
                if (r < M) {
                    C[(size_t)r * N + c]     = tanhf(acc[mt][nt][0] + b0) * 0.5f;
                    C[(size_t)r * N + c + 1] = tanhf(acc[mt][nt][1] + b1) * 0.5f;
                }
                if (r + 8 < M) {
                    C[(size_t)(r + 8) * N + c]     = tanhf(acc[mt][nt][2] + b0) * 0.5f;
                    C[(size_t)(r + 8) * N + c + 1] = tanhf(acc[mt][nt][3] + b1) * 0.5f;
                }
            }
        }
}

// ---------------------------------------------------------------------------
// tf32 GEMM (TN) for value projection; writes V in fp16 (half2 stores).
// ---------------------------------------------------------------------------
__global__ void gemm_tn_tf32(const float* __restrict__ feat, const float* __restrict__ W,
                             const float* __restrict__ bias, int M /*HW*/, int sbase) {
    __shared__ __align__(16) uint32_t As[16][136];
    __shared__ __align__(16) uint32_t Bs[16][72];
    const int tid  = threadIdx.x;
    const int lane = tid & 31;
    const int warp = tid >> 5;
    const int g  = lane >> 2, t4 = lane & 3;
    const int wm = warp >> 1, wn = warp & 1;
    const int m0 = blockIdx.x * 128, n0 = blockIdx.y * 64;
    const int b  = blockIdx.z;
    const int K = D_, N = D_;

    const float* A = feat + (size_t)b * K * M;

    float acc[2][4][4] = {};

    for (int k0 = 0; k0 < K; k0 += 16) {
#pragma unroll
        for (int p = 0; p < 2; ++p) {
            int m = p * 64 + (tid & 15) * 4;
            int k = tid >> 4;
            float4 a4 = make_float4(0.f, 0.f, 0.f, 0.f);
            if (m0 + m < M)
                a4 = *reinterpret_cast<const float4*>(A + (size_t)(k0 + k) * M + m0 + m);
            uint4 u;
            u.x = f2tf32(a4.x); u.y = f2tf32(a4.y); u.z = f2tf32(a4.z); u.w = f2tf32(a4.w);
            *reinterpret_cast<uint4*>(&As[k][m]) = u;
        }
        {
            int kr = tid >> 4, nn = (tid & 15) * 4;
            float4 b4 = *reinterpret_cast<const float4*>(W + (size_t)(k0 + kr) * N + n0 + nn);
            uint4 u;
            u.x = f2tf32(b4.x); u.y = f2tf32(b4.y); u.z = f2tf32(b4.z); u.w = f2tf32(b4.w);
            *reinterpret_cast<uint4*>(&Bs[kr][nn]) = u;
        }
        __syncthreads();
#pragma unroll
        for (int ks = 0; ks < 2; ++ks) {
            const int kb = ks * 8;
            uint32_t af[2][4], bf[4][2];
#pragma unroll
            for (int mt = 0; mt < 2; ++mt) {
                int rb = wm * 32 + mt * 16;
                af[mt][0] = As[kb + t4    ][rb + g    ];
                af[mt][1] = As[kb + t4    ][rb + g + 8];
                af[mt][2] = As[kb + t4 + 4][rb + g    ];
                af[mt][3] = As[kb + t4 + 4][rb + g + 8];
            }
#pragma unroll
            for (int nt = 0; nt < 4; ++nt) {
                int cb = wn * 32 + nt * 8;
                bf[nt][0] = Bs[kb + t4    ][cb + g];
                bf[nt][1] = Bs[kb + t4 + 4][cb + g];
            }
#pragma unroll
            for (int mt = 0; mt < 2; ++mt)
#pragma unroll
                for (int nt = 0; nt < 4; ++nt)
                    mma_tf32(acc[mt][nt], af[mt], bf[nt]);
        }
        __syncthreads();
    }

#pragma unroll
    for (int mt = 0; mt < 2; ++mt)
#pragma unroll
        for (int nt = 0; nt < 4; ++nt) {
            int r = m0 + wm * 32 + mt * 16 + g;
            int c = n0 + wn * 32 + nt * 8 + t4 * 2;
            float b0 = bias[c], b1 = bias[c + 1];
            if (r < M) {
                size_t row = ((size_t)b * S_ + sbase + r) * D_;
                __half2 hv = __floats2half2_rn(acc[mt][nt][0] + b0, acc[mt][nt][1] + b1);
                *reinterpret_cast<__half2*>(&g_Vh[row + c]) = hv;
            }
            if (r + 8 < M) {
                size_t row = ((size_t)b * S_ + sbase + r + 8) * D_;
                __half2 hv = __floats2half2_rn(acc[mt][nt][2] + b0, acc[mt][nt][3] + b1);
                *reinterpret_cast<__half2*>(&g_Vh[row + c]) = hv;
            }
        }
}

// ---------------------------------------------------------------------------
// Softmax over 12 (level,point) logits: one thread per (bq, h); in place.
// ---------------------------------------------------------------------------
__global__ void softmax12(float* __restrict__ att) {
    int i = blockIdx.x * blockDim.x + threadIdx.x;
    if (i >= MQ_ * NH_) return;
    float* p = att + (size_t)(i >> 3) * 96 + (i & 7) * 12;
    float v[12], mx = -1e30f;
#pragma unroll
    for (int j = 0; j < 12; ++j) { v[j] = p[j]; mx = fmaxf(mx, v[j]); }
    float s = 0.f;
#pragma unroll
    for (int j = 0; j < 12; ++j) { v[j] = __expf(v[j] - mx); s += v[j]; }
    float inv = 1.f / s;
#pragma unroll
    for (int j = 0; j < 12; ++j) p[j] = v[j] * inv;
}

// ---------------------------------------------------------------------------
// Sampling: one warp per (b,q), 8 lanes per head (4 fp16 channels each = 8B
// loads, 64B coalesced per head-corner), 4 heads per pass, 2 passes.
// ---------------------------------------------------------------------------
__global__ void sample_kernel(const float* __restrict__ ref) {
    const int warp = (blockIdx.x * blockDim.x + threadIdx.x) >> 5;
    const int lane = threadIdx.x & 31;
    if (warp >= MQ_) return;

    const int bq  = warp;
    const int b   = bq / Q_;
    const int grp = lane >> 3;          // head group 0..3
    const int cl  = (lane & 7) * 4;     // channel offset within head

    const float rx = __ldg(ref + (size_t)bq * 2 + 0);
    const float ry = __ldg(ref + (size_t)bq * 2 + 1);

    const int Wls[3] = {80, 40, 20};
    const int bas[3] = {0, 6400, 8000};

    const __half* Vbase = g_Vh + (size_t)b * S_ * D_;

#pragma unroll
    for (int pass = 0; pass < 2; ++pass) {
        const int h = grp + pass * 4;
        const float* offp = g_OFF + (size_t)bq * 192 + h * 24;
        const float* attp = g_ATT + (size_t)bq * 96 + h * 12;
        const __half* Vb  = Vbase + h * HD_ + cl;

        float4 acc = make_float4(0.f, 0.f, 0.f, 0.f);
#pragma unroll
        for (int l = 0; l < NL_; ++l) {
            const int Wl = Wls[l], base = bas[l];
            const float Wlf = (float)Wl;
#pragma unroll
            for (int p = 0; p < NP_; ++p) {
                const float ox = __ldg(offp + (l * 4 + p) * 2 + 0);
                const float oy = __ldg(offp + (l * 4 + p) * 2 + 1);
                const float w  = __ldg(attp + l * 4 + p);
                const float ix = (rx + ox) * Wlf - 0.5f;
                const float iy = (ry + oy) * Wlf - 0.5f;
                const float x0f = floorf(ix), y0f = floorf(iy);
                const int x0 = (int)x0f, y0 = (int)y0f;
                const float fx = ix - x0f, fy = iy - y0f;
                const float w00 = w * (1.f - fx) * (1.f - fy);
                const float w01 = w * fx * (1.f - fy);
                const float w10 = w * (1.f - fx) * fy;
                const float w11 = w * fx * fy;

                const bool xin0 = (x0 >= 0) && (x0 < Wl);
                const bool xin1 = (x0 + 1 >= 0) && (x0 + 1 < Wl);
                const bool yin0 = (y0 >= 0) && (y0 < Wl);
                const bool yin1 = (y0 + 1 >= 0) && (y0 + 1 < Wl);

#define ACC_CORNER(cond, idx, wgt)                                              \
                if (cond) {                                                     \
                    uint2 u = *reinterpret_cast<const uint2*>(Vb + (size_t)(idx) * D_); \
                    float2 f0 = __half22float2(*reinterpret_cast<__half2*>(&u.x)); \
                    float2 f1 = __half22float2(*reinterpret_cast<__half2*>(&u.y)); \
                    acc.x = fmaf(wgt, f0.x, acc.x); acc.y = fmaf(wgt, f0.y, acc.y); \
                    acc.z = fmaf(wgt, f1.x, acc.z); acc.w = fmaf(wgt, f1.y, acc.w); \
                }

                ACC_CORNER(xin0 && yin0, base + y0 * Wl + x0,           w00)
                ACC_CORNER(xin1 && yin0, base + y0 * Wl + x0 + 1,       w01)
                ACC_CORNER(xin0 && yin1, base + (y0 + 1) * Wl + x0,     w10)
                ACC_CORNER(xin1 && yin1, base + (y0 + 1) * Wl + x0 + 1, w11)
#undef ACC_CORNER
            }
        }
        *reinterpret_cast<float4*>(g_MID + (size_t)bq * D_ + h * HD_ + cl) = acc;
    }
}

// ---------------------------------------------------------------------------
// Launch
// ---------------------------------------------------------------------------
extern "C" void kernel_launch(void* const* d_in, const int* in_sizes, int n_in,
                              void* d_out, int out_size) {
    const float* query = (const float*)d_in[0];
    const float* feat0 = (const float*)d_in[1];
    const float* feat1 = (const float*)d_in[2];
    const float* feat2 = (const float*)d_in[3];
    const float* refp  = (const float*)d_in[4];
    const float* W_off = (const float*)d_in[5];
    const float* b_off = (const float*)d_in[6];
    const float* W_att = (const float*)d_in[7];
    const float* b_att = (const float*)d_in[8];
    const float* W_val = (const float*)d_in[9];
    const float* b_val = (const float*)d_in[10];
    const float* W_out = (const float*)d_in[11];
    const float* b_out = (const float*)d_in[12];
    float* out = (float*)d_out;

    float* pOFF; cudaGetSymbolAddress((void**)&pOFF, g_OFF);
    float* pATT; cudaGetSymbolAddress((void**)&pATT, g_ATT);
    float* pMID; cudaGetSymbolAddress((void**)&pMID, g_MID);

    dim3 blk(256);

    // 1) value projection per level (tf32 tensor cores, fp16 V output)
    gemm_tn_tf32<<<dim3(50, 4, B_), blk>>>(feat0, W_val, b_val, 6400, 0);
    gemm_tn_tf32<<<dim3(13, 4, B_), blk>>>(feat1, W_val, b_val, 1600, 6400);
    gemm_tn_tf32<<<dim3( 4, 4, B_), blk>>>(feat2, W_val, b_val,  400, 8000);

    // 2) offset logits (3xTF32 tensor cores, fused tanh*0.5)
    gemm_nn_tanh_3x<<<dim3((MQ_ + 127) / 128, 3), blk>>>(query, W_off, b_off, pOFF, MQ_, 192, D_);

    // 3) attention logits (tf32) + softmax
    gemm_nn_tf32<<<dim3((MQ_ + 127) / 128, 2), blk>>>(query, W_att, b_att, pATT, MQ_, 96, D_);
    softmax12<<<(MQ_ * NH_ + 255) / 256, 256>>>(pATT);

    // 4) bilinear sampling -> MID (warp per (b,q), fp16 gathers)
    sample_kernel<<<(MQ_ + 7) / 8, 256>>>(refp);

    // 5) output projection (tf32)
    gemm_nn_tf32<<<dim3((MQ_ + 127) / 128, 4), blk>>>(pMID, W_out, b_out, out, MQ_, D_, D_);
}

// round 8
// speedup vs baseline: 2.3670x; 1.0768x over previous
#include <cuda_runtime.h>
#include <cuda_fp16.h>
#include <cuda_bf16.h>
#include <cstdint>

// ---------------------------------------------------------------------------
// MultiScaleDETR deformable attention.
// B=4, Q=8400, D=256, nH=8, hd=32, L=3 (80x80,40x40,20x20), P=4.
// tf32 tensor-core GEMMs; 3xBF16 split-precision (m16n8k16) for offsets;
// V stored fp16 for gather traffic.
// ---------------------------------------------------------------------------

#define B_    4
#define Q_    8400
#define D_    256
#define NH_   8
#define HD_   32
#define NL_   3
#define NP_   4
#define S_    8400
#define MQ_   (B_ * Q_)      // 33600

__device__ __half g_Vh [B_ * S_ * D_];  // value projection [b][s][d], fp16
__device__ float  g_OFF[MQ_ * 192];     // tanh(offset_logit)*0.5
__device__ float  g_ATT[MQ_ * 96];      // attn logits -> softmax'ed in place
__device__ float  g_MID[MQ_ * D_];      // attention output pre-W_out

// ---------------------------------------------------------------------------
// mma helpers
// ---------------------------------------------------------------------------
__device__ __forceinline__ uint32_t f2tf32(float f) {
    uint32_t u;
    asm("cvt.rna.tf32.f32 %0, %1;" : "=r"(u) : "f"(f));
    return u;
}

__device__ __forceinline__ void mma_tf32(float* d, const uint32_t* a, const uint32_t* b) {
    asm volatile(
        "mma.sync.aligned.m16n8k8.row.col.f32.tf32.tf32.f32 "
        "{%0,%1,%2,%3}, {%4,%5,%6,%7}, {%8,%9}, {%0,%1,%2,%3};\n"
        : "+f"(d[0]), "+f"(d[1]), "+f"(d[2]), "+f"(d[3])
        : "r"(a[0]), "r"(a[1]), "r"(a[2]), "r"(a[3]), "r"(b[0]), "r"(b[1]));
}

__device__ __forceinline__ void mma_bf16(float* d, const uint32_t* a, const uint32_t* b) {
    asm volatile(
        "mma.sync.aligned.m16n8k16.row.col.f32.bf16.bf16.f32 "
        "{%0,%1,%2,%3}, {%4,%5,%6,%7}, {%8,%9}, {%0,%1,%2,%3};\n"
        : "+f"(d[0]), "+f"(d[1]), "+f"(d[2]), "+f"(d[3])
        : "r"(a[0]), "r"(a[1]), "r"(a[2]), "r"(a[3]), "r"(b[0]), "r"(b[1]));
}

__device__ __forceinline__ uint32_t pack_bf16(__nv_bfloat16 a, __nv_bfloat16 b) {
    __nv_bfloat162 h; h.x = a; h.y = b;
    return *reinterpret_cast<uint32_t*>(&h);
}

// ---------------------------------------------------------------------------
// tf32 GEMM (NN): C[M,N] = A[M,K](row) @ B[K,N](row) + bias
// 128x64x16 tile, 256 threads = 8 warps (4m x 2n), warp tile 32x32.
// ---------------------------------------------------------------------------
__global__ void gemm_nn_tf32(const float* __restrict__ A, const float* __restrict__ Bm,
                             const float* __restrict__ bias, float* __restrict__ C,
                             int M, int N, int K) {
    __shared__ __align__(16) uint32_t As[128][20];
    __shared__ __align__(16) uint32_t Bs[16][72];
    const int tid  = threadIdx.x;
    const int lane = tid & 31;
    const int warp = tid >> 5;
    const int g  = lane >> 2, t4 = lane & 3;
    const int wm = warp >> 1, wn = warp & 1;
    const int m0 = blockIdx.x * 128, n0 = blockIdx.y * 64;

    float acc[2][4][4] = {};

    for (int k0 = 0; k0 < K; k0 += 16) {
#pragma unroll
        for (int p = 0; p < 2; ++p) {
            int m  = p * 64 + (tid >> 2);
            int kk = (tid & 3) * 4;
            float4 a4 = make_float4(0.f, 0.f, 0.f, 0.f);
            int gm = m0 + m;
            if (gm < M) a4 = *reinterpret_cast<const float4*>(A + (size_t)gm * K + k0 + kk);
            uint4 u;
            u.x = f2tf32(a4.x); u.y = f2tf32(a4.y); u.z = f2tf32(a4.z); u.w = f2tf32(a4.w);
            *reinterpret_cast<uint4*>(&As[m][kk]) = u;
        }
        {
            int kr = tid >> 4, nn = (tid & 15) * 4;
            float4 b4 = make_float4(0.f, 0.f, 0.f, 0.f);
            if (n0 + nn < N)
                b4 = *reinterpret_cast<const float4*>(Bm + (size_t)(k0 + kr) * N + n0 + nn);
            uint4 u;
            u.x = f2tf32(b4.x); u.y = f2tf32(b4.y); u.z = f2tf32(b4.z); u.w = f2tf32(b4.w);
            *reinterpret_cast<uint4*>(&Bs[kr][nn]) = u;
        }
        __syncthreads();
#pragma unroll
        for (int ks = 0; ks < 2; ++ks) {
            const int kb = ks * 8;
            uint32_t af[2][4], bf[4][2];
#pragma unroll
            for (int mt = 0; mt < 2; ++mt) {
                int rb = wm * 32 + mt * 16;
                af[mt][0] = As[rb + g    ][kb + t4    ];
                af[mt][1] = As[rb + g + 8][kb + t4    ];
                af[mt][2] = As[rb + g    ][kb + t4 + 4];
                af[mt][3] = As[rb + g + 8][kb + t4 + 4];
            }
#pragma unroll
            for (int nt = 0; nt < 4; ++nt) {
                int cb = wn * 32 + nt * 8;
                bf[nt][0] = Bs[kb + t4    ][cb + g];
                bf[nt][1] = Bs[kb + t4 + 4][cb + g];
            }
#pragma unroll
            for (int mt = 0; mt < 2; ++mt)
#pragma unroll
                for (int nt = 0; nt < 4; ++nt)
                    mma_tf32(acc[mt][nt], af[mt], bf[nt]);
        }
        __syncthreads();
    }

#pragma unroll
    for (int mt = 0; mt < 2; ++mt)
#pragma unroll
        for (int nt = 0; nt < 4; ++nt) {
            int r = m0 + wm * 32 + mt * 16 + g;
            int c = n0 + wn * 32 + nt * 8 + t4 * 2;
            if (c < N) {
                float b0 = bias[c], b1 = bias[c + 1];
                if (r < M) {
                    C[(size_t)r * N + c]     = acc[mt][nt][0] + b0;
                    C[(size_t)r * N + c + 1] = acc[mt][nt][1] + b1;
                }
                if (r + 8 < M) {
                    C[(size_t)(r + 8) * N + c]     = acc[mt][nt][2] + b0;
                    C[(size_t)(r + 8) * N + c + 1] = acc[mt][nt][3] + b1;
                }
            }
        }
}

// ---------------------------------------------------------------------------
// 3xBF16 split GEMM (NN) with tanh(x)*0.5 epilogue.
// a = hi + lo (bf16 splits); acc += hi*LO + lo*HI + hi*HI via m16n8k16.
// Packed-k smem: As2[m][kk] = (bf16 k=2kk, k=2kk+1); Bs2[kk][n] likewise.
// Half the LDS and half the tensor cycles of the 3xTF32 version.
// ---------------------------------------------------------------------------
__global__ void gemm_nn_tanh_3xbf16(const float* __restrict__ A, const float* __restrict__ Bm,
                                    const float* __restrict__ bias, float* __restrict__ C,
                                    int M, int N, int K) {
    __shared__ __align__(16) uint32_t AsH[128][12];  // pitch 12: frag loads conflict-free
    __shared__ __align__(16) uint32_t AsL[128][12];
    __shared__ __align__(16) uint32_t BsH[8][72];    // pitch 72 (mod 32 = 8): conflict-free
    __shared__ __align__(16) uint32_t BsL[8][72];
    const int tid  = threadIdx.x;
    const int lane = tid & 31;
    const int warp = tid >> 5;
    const int g  = lane >> 2, t4 = lane & 3;
    const int wm = warp >> 1, wn = warp & 1;
    const int m0 = blockIdx.x * 128, n0 = blockIdx.y * 64;

    float acc[2][4][4] = {};

    for (int k0 = 0; k0 < K; k0 += 16) {
        // stage A: 128x16 floats -> bf16 hi/lo pairs packed along k
#pragma unroll
        for (int p = 0; p < 2; ++p) {
            int m   = p * 64 + (tid >> 2);
            int kk4 = (tid & 3) * 4;          // k offset (4 floats)
            float4 a4 = make_float4(0.f, 0.f, 0.f, 0.f);
            int gm = m0 + m;
            if (gm < M) a4 = *reinterpret_cast<const float4*>(A + (size_t)gm * K + k0 + kk4);
            __nv_bfloat16 h0 = __float2bfloat16_rn(a4.x);
            __nv_bfloat16 h1 = __float2bfloat16_rn(a4.y);
            __nv_bfloat16 h2 = __float2bfloat16_rn(a4.z);
            __nv_bfloat16 h3 = __float2bfloat16_rn(a4.w);
            __nv_bfloat16 l0 = __float2bfloat16_rn(a4.x - __bfloat162float(h0));
            __nv_bfloat16 l1 = __float2bfloat16_rn(a4.y - __bfloat162float(h1));
            __nv_bfloat16 l2 = __float2bfloat16_rn(a4.z - __bfloat162float(h2));
            __nv_bfloat16 l3 = __float2bfloat16_rn(a4.w - __bfloat162float(h3));
            int kp = (tid & 3) * 2;           // packed-pair index
            AsH[m][kp]     = pack_bf16(h0, h1);
            AsH[m][kp + 1] = pack_bf16(h2, h3);
            AsL[m][kp]     = pack_bf16(l0, l1);
            AsL[m][kp + 1] = pack_bf16(l2, l3);
        }
        // stage B: 16x64 floats; thread owns n = tid&63, kk in {tid>>6, tid>>6 + 4}
        {
            int n  = tid & 63;
            int k2 = tid >> 6;                // 0..3
#pragma unroll
            for (int q = 0; q < 2; ++q) {
                int kk = k2 + q * 4;          // packed-pair row 0..7
                float v0 = Bm[(size_t)(k0 + 2 * kk)     * N + n0 + n];
                float v1 = Bm[(size_t)(k0 + 2 * kk + 1) * N + n0 + n];
                __nv_bfloat16 h0 = __float2bfloat16_rn(v0);
                __nv_bfloat16 h1 = __float2bfloat16_rn(v1);
                __nv_bfloat16 l0 = __float2bfloat16_rn(v0 - __bfloat162float(h0));
                __nv_bfloat16 l1 = __float2bfloat16_rn(v1 - __bfloat162float(h1));
                BsH[kk][n] = pack_bf16(h0, h1);
                BsL[kk][n] = pack_bf16(l0, l1);
            }
        }
        __syncthreads();

        uint32_t afH[2][4], afL[2][4], bfH[4][2], bfL[4][2];
#pragma unroll
        for (int mt = 0; mt < 2; ++mt) {
            int rb = wm * 32 + mt * 16;
            afH[mt][0] = AsH[rb + g    ][t4    ];
            afH[mt][1] = AsH[rb + g + 8][t4    ];
            afH[mt][2] = AsH[rb + g    ][t4 + 4];
            afH[mt][3] = AsH[rb + g + 8][t4 + 4];
            afL[mt][0] = AsL[rb + g    ][t4    ];
            afL[mt][1] = AsL[rb + g + 8][t4    ];
            afL[mt][2] = AsL[rb + g    ][t4 + 4];
            afL[mt][3] = AsL[rb + g + 8][t4 + 4];
        }
#pragma unroll
        for (int nt = 0; nt < 4; ++nt) {
            int cb = wn * 32 + nt * 8;
            bfH[nt][0] = BsH[t4    ][cb + g];
            bfH[nt][1] = BsH[t4 + 4][cb + g];
            bfL[nt][0] = BsL[t4    ][cb + g];
            bfL[nt][1] = BsL[t4 + 4][cb + g];
        }
#pragma unroll
        for (int mt = 0; mt < 2; ++mt)
#pragma unroll
            for (int nt = 0; nt < 4; ++nt)
                mma_bf16(acc[mt][nt], afH[mt], bfL[nt]);
#pragma unroll
        for (int mt = 0; mt < 2; ++mt)
#pragma unroll
            for (int nt = 0; nt < 4; ++nt)
                mma_bf16(acc[mt][nt], afL[mt], bfH[nt]);
#pragma unroll
        for (int mt = 0; mt < 2; ++mt)
#pragma unroll
            for (int nt = 0; nt < 4; ++nt)
                mma_bf16(acc[mt][nt], afH[mt], bfH[nt]);
        __syncthreads();
    }

#pragma unroll
    for (int mt = 0; mt < 2; ++mt)
#pragma unroll
        for (int nt = 0; nt < 4; ++nt) {
            int r = m0 + wm * 32 + mt * 16 + g;
            int c = n0 + wn * 32 + nt * 8 + t4 * 2;
            float b0 = bias[c], b1 = bias[c + 1];
            if (r < M) {
                C[(size_t)r * N + c]     = tanhf(acc[mt][nt][0] + b0) * 0.5f;
                C[(size_t)r * N + c + 1] = tanhf(acc[mt][nt][1] + b1) * 0.5f;
            }
            if (r + 8 < M) {
                C[(size_t)(r + 8) * N + c]     = tanhf(acc[mt][nt][2] + b0) * 0.5f;
                C[(size_t)(r + 8) * N + c + 1] = tanhf(acc[mt][nt][3] + b1) * 0.5f;
            }
        }
}

// ---------------------------------------------------------------------------
// tf32 GEMM (TN) for value projection; writes V in fp16 (half2 stores).
// ---------------------------------------------------------------------------
__global__ void gemm_tn_tf32(const float* __restrict__ feat, const float* __restrict__ W,
                             const float* __restrict__ bias, int M /*HW*/, int sbase) {
    __shared__ __align__(16) uint32_t As[16][136];
    __shared__ __align__(16) uint32_t Bs[16][72];
    const int tid  = threadIdx.x;
    const int lane = tid & 31;
    const int warp = tid >> 5;
    const int g  = lane >> 2, t4 = lane & 3;
    const int wm = warp >> 1, wn = warp & 1;
    const int m0 = blockIdx.x * 128, n0 = blockIdx.y * 64;
    const int b  = blockIdx.z;
    const int K = D_, N = D_;

    const float* A = feat + (size_t)b * K * M;

    float acc[2][4][4] = {};

    for (int k0 = 0; k0 < K; k0 += 16) {
#pragma unroll
        for (int p = 0; p < 2; ++p) {
            int m = p * 64 + (tid & 15) * 4;
            int k = tid >> 4;
            float4 a4 = make_float4(0.f, 0.f, 0.f, 0.f);
            if (m0 + m < M)
                a4 = *reinterpret_cast<const float4*>(A + (size_t)(k0 + k) * M + m0 + m);
            uint4 u;
            u.x = f2tf32(a4.x); u.y = f2tf32(a4.y); u.z = f2tf32(a4.z); u.w = f2tf32(a4.w);
            *reinterpret_cast<uint4*>(&As[k][m]) = u;
        }
        {
            int kr = tid >> 4, nn = (tid & 15) * 4;
            float4 b4 = *reinterpret_cast<const float4*>(W + (size_t)(k0 + kr) * N + n0 + nn);
            uint4 u;
            u.x = f2tf32(b4.x); u.y = f2tf32(b4.y); u.z = f2tf32(b4.z); u.w = f2tf32(b4.w);
            *reinterpret_cast<uint4*>(&Bs[kr][nn]) = u;
        }
        __syncthreads();
#pragma unroll
        for (int ks = 0; ks < 2; ++ks) {
            const int kb = ks * 8;
            uint32_t af[2][4], bf[4][2];
#pragma unroll
            for (int mt = 0; mt < 2; ++mt) {
                int rb = wm * 32 + mt * 16;
                af[mt][0] = As[kb + t4    ][rb + g    ];
                af[mt][1] = As[kb + t4    ][rb + g + 8];
                af[mt][2] = As[kb + t4 + 4][rb + g    ];
                af[mt][3] = As[kb + t4 + 4][rb + g + 8];
            }
#pragma unroll
            for (int nt = 0; nt < 4; ++nt) {
                int cb = wn * 32 + nt * 8;
                bf[nt][0] = Bs[kb + t4    ][cb + g];
                bf[nt][1] = Bs[kb + t4 + 4][cb + g];
            }
#pragma unroll
            for (int mt = 0; mt < 2; ++mt)
#pragma unroll
                for (int nt = 0; nt < 4; ++nt)
                    mma_tf32(acc[mt][nt], af[mt], bf[nt]);
        }
        __syncthreads();
    }

#pragma unroll
    for (int mt = 0; mt < 2; ++mt)
#pragma unroll
        for (int nt = 0; nt < 4; ++nt) {
            int r = m0 + wm * 32 + mt * 16 + g;
            int c = n0 + wn * 32 + nt * 8 + t4 * 2;
            float b0 = bias[c], b1 = bias[c + 1];
            if (r < M) {
                size_t row = ((size_t)b * S_ + sbase + r) * D_;
                __half2 hv = __floats2half2_rn(acc[mt][nt][0] + b0, acc[mt][nt][1] + b1);
                *reinterpret_cast<__half2*>(&g_Vh[row + c]) = hv;
            }
            if (r + 8 < M) {
                size_t row = ((size_t)b * S_ + sbase + r + 8) * D_;
                __half2 hv = __floats2half2_rn(acc[mt][nt][2] + b0, acc[mt][nt][3] + b1);
                *reinterpret_cast<__half2*>(&g_Vh[row + c]) = hv;
            }
        }
}

// ---------------------------------------------------------------------------
// Softmax over 12 (level,point) logits: one thread per (bq, h); in place.
// ---------------------------------------------------------------------------
__global__ void softmax12(float* __restrict__ att) {
    int i = blockIdx.x * blockDim.x + threadIdx.x;
    if (i >= MQ_ * NH_) return;
    float* p = att + (size_t)(i >> 3) * 96 + (i & 7) * 12;
    float v[12], mx = -1e30f;
#pragma unroll
    for (int j = 0; j < 12; ++j) { v[j] = p[j]; mx = fmaxf(mx, v[j]); }
    float s = 0.f;
#pragma unroll
    for (int j = 0; j < 12; ++j) { v[j] = __expf(v[j] - mx); s += v[j]; }
    float inv = 1.f / s;
#pragma unroll
    for (int j = 0; j < 12; ++j) p[j] = v[j] * inv;
}

// ---------------------------------------------------------------------------
// Sampling: one warp per (bq, pass). 8 lanes per head (4 fp16 channels each),
// 4 heads per warp. Dual accumulators to split the FFMA dependency chain.
// ---------------------------------------------------------------------------
__global__ void sample_kernel(const float* __restrict__ ref) {
    const int gw   = (blockIdx.x * blockDim.x + threadIdx.x) >> 5;
    const int lane = threadIdx.x & 31;
    if (gw >= MQ_ * 2) return;

    const int bq   = gw >> 1;
    const int pass = gw & 1;
    const int b    = bq / Q_;
    const int grp  = lane >> 3;         // head group 0..3
    const int cl   = (lane & 7) * 4;    // channel offset within head

    const float rx = __ldg(ref + (size_t)bq * 2 + 0);
    const float ry = __ldg(ref + (size_t)bq * 2 + 1);

    const int Wls[3] = {80, 40, 20};
    const int bas[3] = {0, 6400, 8000};

    const int h = grp + pass * 4;
    const float* offp = g_OFF + (size_t)bq * 192 + h * 24;
    const float* attp = g_ATT + (size_t)bq * 96 + h * 12;
    const __half* Vb  = g_Vh + (size_t)b * S_ * D_ + h * HD_ + cl;

    float4 acc0 = make_float4(0.f, 0.f, 0.f, 0.f);
    float4 acc1 = make_float4(0.f, 0.f, 0.f, 0.f);

#pragma unroll
    for (int l = 0; l < NL_; ++l) {
        const int Wl = Wls[l], base = bas[l];
        const float Wlf = (float)Wl;
#pragma unroll
        for (int p = 0; p < NP_; ++p) {
            float4& acc = (p & 1) ? acc1 : acc0;
            const float ox = __ldg(offp + (l * 4 + p) * 2 + 0);
            const float oy = __ldg(offp + (l * 4 + p) * 2 + 1);
            const float w  = __ldg(attp + l * 4 + p);
            const float ix = (rx + ox) * Wlf - 0.5f;
            const float iy = (ry + oy) * Wlf - 0.5f;
            const float x0f = floorf(ix), y0f = floorf(iy);
            const int x0 = (int)x0f, y0 = (int)y0f;
            const float fx = ix - x0f, fy = iy - y0f;
            const float w00 = w * (1.f - fx) * (1.f - fy);
            const float w01 = w * fx * (1.f - fy);
            const float w10 = w * (1.f - fx) * fy;
            const float w11 = w * fx * fy;

            const bool xin0 = (x0 >= 0) && (x0 < Wl);
            const bool xin1 = (x0 + 1 >= 0) && (x0 + 1 < Wl);
            const bool yin0 = (y0 >= 0) && (y0 < Wl);
            const bool yin1 = (y0 + 1 >= 0) && (y0 + 1 < Wl);

#define ACC_CORNER(cond, idx, wgt)                                              \
            if (cond) {                                                         \
                uint2 u = *reinterpret_cast<const uint2*>(Vb + (size_t)(idx) * D_); \
                float2 f0 = __half22float2(*reinterpret_cast<__half2*>(&u.x));  \
                float2 f1 = __half22float2(*reinterpret_cast<__half2*>(&u.y));  \
                acc.x = fmaf(wgt, f0.x, acc.x); acc.y = fmaf(wgt, f0.y, acc.y); \
                acc.z = fmaf(wgt, f1.x, acc.z); acc.w = fmaf(wgt, f1.y, acc.w); \
            }

            ACC_CORNER(xin0 && yin0, base + y0 * Wl + x0,           w00)
            ACC_CORNER(xin1 && yin0, base + y0 * Wl + x0 + 1,       w01)
            ACC_CORNER(xin0 && yin1, base + (y0 + 1) * Wl + x0,     w10)
            ACC_CORNER(xin1 && yin1, base + (y0 + 1) * Wl + x0 + 1, w11)
#undef ACC_CORNER
        }
    }

    float4 acc;
    acc.x = acc0.x + acc1.x; acc.y = acc0.y + acc1.y;
    acc.z = acc0.z + acc1.z; acc.w = acc0.w + acc1.w;
    *reinterpret_cast<float4*>(g_MID + (size_t)bq * D_ + h * HD_ + cl) = acc;
}

// ---------------------------------------------------------------------------
// Launch
// ---------------------------------------------------------------------------
extern "C" void kernel_launch(void* const* d_in, const int* in_sizes, int n_in,
                              void* d_out, int out_size) {
    const float* query = (const float*)d_in[0];
    const float* feat0 = (const float*)d_in[1];
    const float* feat1 = (const float*)d_in[2];
    const float* feat2 = (const float*)d_in[3];
    const float* refp  = (const float*)d_in[4];
    const float* W_off = (const float*)d_in[5];
    const float* b_off = (const float*)d_in[6];
    const float* W_att = (const float*)d_in[7];
    const float* b_att = (const float*)d_in[8];
    const float* W_val = (const float*)d_in[9];
    const float* b_val = (const float*)d_in[10];
    const float* W_out = (const float*)d_in[11];
    const float* b_out = (const float*)d_in[12];
    float* out = (float*)d_out;

    float* pOFF; cudaGetSymbolAddress((void**)&pOFF, g_OFF);
    float* pATT; cudaGetSymbolAddress((void**)&pATT, g_ATT);
    float* pMID; cudaGetSymbolAddress((void**)&pMID, g_MID);

    dim3 blk(256);

    // 1) value projection per level (tf32 tensor cores, fp16 V output)
    gemm_tn_tf32<<<dim3(50, 4, B_), blk>>>(feat0, W_val, b_val, 6400, 0);
    gemm_tn_tf32<<<dim3(13, 4, B_), blk>>>(feat1, W_val, b_val, 1600, 6400);
    gemm_tn_tf32<<<dim3( 4, 4, B_), blk>>>(feat2, W_val, b_val,  400, 8000);

    // 2) offset logits (3xBF16 split tensor cores, fused tanh*0.5)
    gemm_nn_tanh_3xbf16<<<dim3((MQ_ + 127) / 128, 3), blk>>>(query, W_off, b_off, pOFF, MQ_, 192, D_);

    // 3) attention logits (tf32) + softmax
    gemm_nn_tf32<<<dim3((MQ_ + 127) / 128, 2), blk>>>(query, W_att, b_att, pATT, MQ_, 96, D_);
    softmax12<<<(MQ_ * NH_ + 255) / 256, 256>>>(pATT);

    // 4) bilinear sampling -> MID (warp per (bq, pass), fp16 gathers)
    sample_kernel<<<(MQ_ * 2 + 7) / 8, 256>>>(refp);

    // 5) output projection (tf32)
    gemm_nn_tf32<<<dim3((MQ_ + 127) / 128, 4), blk>>>(pMID, W_out, b_out, out, MQ_, D_, D_);
}